// round 13
// baseline (speedup 1.0000x reference)
#include <cuda_runtime.h>
#include <cooperative_groups.h>
#include <math.h>

namespace cg = cooperative_groups;

#define BN 16
#define UPD 512
#define NPIX (UPD*UPD)
#define PATCH 120
#define NM 4

// ---------------- static device scratch (zero-initialized at load) ----------------
__device__ float g_inv[3*BN*6];                 // inverse thetas: [which][b][6]
__device__ float g_bufA[BN*NPIX];               // pred_trans
__device__ float g_bufB[BN*NPIX];               // pred_rot
__device__ float g_rm2[NM*BN*NPIX];             // mask after g2 sample (zero outside boxes)
__device__ int4  g_srcpart[NM*8];               // per-j partial src bboxes
__device__ float g_com[NM*BN*3];                // per (j,b): tot, sx, sy
__device__ float g_patch[BN*PATCH*PATCH];       // revise patch snapshot

// ---------------- helpers ----------------
// Read-only-source sampler (masks/base only — never written in-kernel)
__device__ __forceinline__ float bilin_ro(const float* __restrict__ s,
                                          float gx, float gy) {
    float x = ((gx + 1.0f) * 512.0f - 1.0f) * 0.5f;
    float y = ((gy + 1.0f) * 512.0f - 1.0f) * 0.5f;
    float xf = floorf(x), yf = floorf(y);
    int x0 = (int)xf, y0 = (int)yf;
    float wx = x - xf, wy = y - yf;
    int x1 = x0 + 1, y1 = y0 + 1;
    bool xi0 = (x0 >= 0) && (x0 < UPD);
    bool xi1 = (x1 >= 0) && (x1 < UPD);
    bool yi0 = (y0 >= 0) && (y0 < UPD);
    bool yi1 = (y1 >= 0) && (y1 < UPD);
    float v00 = 0.f, v01 = 0.f, v10 = 0.f, v11 = 0.f;
    if (yi0) {
        const float* row = s + (y0 << 9);
        if (xi0) v00 = __ldg(row + x0);
        if (xi1) v01 = __ldg(row + x1);
    }
    if (yi1) {
        const float* row = s + (y1 << 9);
        if (xi0) v10 = __ldg(row + x0);
        if (xi1) v11 = __ldg(row + x1);
    }
    return (1.f - wx) * (1.f - wy) * v00 + wx * (1.f - wy) * v01
         + (1.f - wx) * wy * v10 + wx * wy * v11;
}

// Sampler for buffers WRITTEN earlier in the same kernel: plain loads only
// (no __ldg — the read-only path is UB for data written within the kernel;
// grid.sync() fencing covers plain global loads).
__device__ __forceinline__ float bilin_rw(const float* s, float gx, float gy) {
    float x = ((gx + 1.0f) * 512.0f - 1.0f) * 0.5f;
    float y = ((gy + 1.0f) * 512.0f - 1.0f) * 0.5f;
    float xf = floorf(x), yf = floorf(y);
    int x0 = (int)xf, y0 = (int)yf;
    float wx = x - xf, wy = y - yf;
    int x1 = x0 + 1, y1 = y0 + 1;
    bool xi0 = (x0 >= 0) && (x0 < UPD);
    bool xi1 = (x1 >= 0) && (x1 < UPD);
    bool yi0 = (y0 >= 0) && (y0 < UPD);
    bool yi1 = (y1 >= 0) && (y1 < UPD);
    float v00 = 0.f, v01 = 0.f, v10 = 0.f, v11 = 0.f;
    if (yi0) {
        const float* row = s + (y0 << 9);
        if (xi0) v00 = row[x0];
        if (xi1) v01 = row[x1];
    }
    if (yi1) {
        const float* row = s + (y1 << 9);
        if (xi0) v10 = row[x0];
        if (xi1) v11 = row[x1];
    }
    return (1.f - wx) * (1.f - wy) * v00 + wx * (1.f - wy) * v01
         + (1.f - wx) * wy * v10 + wx * wy * v11;
}

__device__ __forceinline__ void preimage_px(const float* th,
        float ya, float yb, float xa, float xb,
        int& ir0, int& ir1, int& ic0, int& ic1) {
    float gxa = (2.f * xa + 1.f) / 512.f - 1.f, gxb = (2.f * xb + 1.f) / 512.f - 1.f;
    float gya = (2.f * ya + 1.f) / 512.f - 1.f, gyb = (2.f * yb + 1.f) / 512.f - 1.f;
    float det = th[0] * th[4] - th[1] * th[3];
    float Xmin = 1e30f, Xmax = -1e30f, Ymin = 1e30f, Ymax = -1e30f;
    #pragma unroll
    for (int u = 0; u < 4; u++) {
        float gx = (u & 1) ? gxb : gxa;
        float gy = (u & 2) ? gyb : gya;
        float rx = gx - th[2], ry = gy - th[5];
        float X = ( th[4] * rx - th[1] * ry) / det;
        float Y = (-th[3] * rx + th[0] * ry) / det;
        Xmin = fminf(Xmin, X); Xmax = fmaxf(Xmax, X);
        Ymin = fminf(Ymin, Y); Ymax = fmaxf(Ymax, Y);
    }
    float jmin = ((Xmin + 1.f) * 512.f - 1.f) * 0.5f;
    float jmax = ((Xmax + 1.f) * 512.f - 1.f) * 0.5f;
    float imin = ((Ymin + 1.f) * 512.f - 1.f) * 0.5f;
    float imax = ((Ymax + 1.f) * 512.f - 1.f) * 0.5f;
    ir0 = max(0,   (int)floorf(imin) - 1);
    ir1 = min(511, (int)ceilf(imax) + 1);
    ic0 = max(0,   (int)floorf(jmin) - 1);
    ic1 = min(511, (int)ceilf(jmax) + 1);
}

// combine source-mask bbox partials for mask j
__device__ __forceinline__ void combine_srcbox(int j, int& r0, int& r1, int& c0, int& c1) {
    r0 = 1 << 20; r1 = -1; c0 = 1 << 20; c1 = -1;
    #pragma unroll
    for (int k = 0; k < 8; k++) {
        int4 p = g_srcpart[j * 8 + k];
        r0 = min(r0, p.x); r1 = max(r1, p.y);
        c0 = min(c0, p.z); c1 = max(c1, p.w);
    }
}

// warp stage: square 32x32 tiles, block=256 threads as (32,8), 4 rows/thread
__device__ __forceinline__ void warp_stage(const float* src, float* dst, float* dst2,
                                           int thoff, int bid0, int nblocks, int tid) {
    int tidx = tid & 31, tidy = tid >> 5;
    for (int t = bid0; t < 4096; t += nblocks) {
        int b = t >> 8, ty = (t >> 4) & 15, tx = t & 15;
        const float* th = g_inv + (thoff + b) * 6;
        float t0 = th[0], t1 = th[1], t2 = th[2], t3 = th[3], t4 = th[4], t5 = th[5];
        int j = tx * 32 + tidx;
        int i0 = ty * 32 + tidy;
        float X = (float)(2 * j + 1) / 512.0f - 1.0f;
        float gxX = t0 * X + t2;
        float gyX = t3 * X + t5;
        const float* s = src + b * NPIX;
        float v[4];
        #pragma unroll
        for (int q = 0; q < 4; q++) {
            int i = i0 + q * 8;
            float Y = (float)(2 * i + 1) / 512.0f - 1.0f;
            v[q] = bilin_rw(s, gxX + t1 * Y, gyX + t4 * Y);
        }
        int base_idx = b * NPIX + (i0 << 9) + j;
        #pragma unroll
        for (int q = 0; q < 4; q++) {
            dst[base_idx + (q << 12)] = v[q];
            if (dst2) dst2[base_idx + (q << 12)] = v[q];
        }
    }
}

// ---------------- THE mega-kernel (cooperative) ----------------
__global__ void __launch_bounds__(256, 6) k_mega(
    const float* __restrict__ base, const float* __restrict__ sc,
    const float* __restrict__ ro, const float* __restrict__ tr,
    const float* __restrict__ adj, const float* __restrict__ masks,
    float* out)
{
    cg::grid_group grid = cg::this_grid();
    int bid = blockIdx.x, G = gridDim.x, tid = threadIdx.x;
    float* seg0 = out;                             // base_inp
    float* seg1 = out + (size_t)BN * NPIX;         // pred_input
    float* seg2 = out + 2 * (size_t)BN * NPIX;     // pred_revise
    float* seg3 = out + 3 * (size_t)BN * NPIX;     // masks_rot

    __shared__ float sh1[256], sh2[256], sh3[256];
    __shared__ int   si0[256], si1[256], si2[256], si3[256];
    __shared__ float sh_thr;
    __shared__ int   sh_xy[2];

    // ======== stage 0: inv + srcbox partials + zero seg3 + resize ========
    if (bid == 0 && tid < 3 * BN) {
        int w = tid / BN, b = tid % BN;
        const float* src = (w == 0) ? sc : ((w == 1) ? ro : tr);
        const float* m = src + b * 6;
        float a = m[0], bb = m[1], c = m[2], d = m[3], e = m[4], f = m[5];
        float det = a * e - bb * d;
        float ia = e / det, ib = -bb / det, id = -d / det, ie = a / det;
        float ic  = -(ia * c + ib * f);
        float iff = -(id * c + ie * f);
        float* o = g_inv + tid * 6;
        o[0] = ia; o[1] = ib; o[2] = ic; o[3] = id; o[4] = ie; o[5] = iff;
    }
    if (bid >= 1 && bid < 33) {
        int idx = bid - 1, j = idx >> 3, seg = idx & 7;
        const float* m = masks + j * NPIX;
        int bbase = seg * (NPIX / 8);
        int rmin = 1 << 20, rmax = -1, cmin = 1 << 20, cmax = -1;
        for (int k = tid; k < NPIX / 8; k += 256) {
            int g = bbase + k;
            if (__ldg(m + g) != 0.0f) {
                int r = g >> 9, c = g & 511;
                rmin = min(rmin, r); rmax = max(rmax, r);
                cmin = min(cmin, c); cmax = max(cmax, c);
            }
        }
        si0[tid] = rmin; si1[tid] = rmax; si2[tid] = cmin; si3[tid] = cmax;
        __syncthreads();
        for (int s = 128; s > 0; s >>= 1) {
            if (tid < s) {
                si0[tid] = min(si0[tid], si0[tid + s]);
                si1[tid] = max(si1[tid], si1[tid + s]);
                si2[tid] = min(si2[tid], si2[tid + s]);
                si3[tid] = max(si3[tid], si3[tid + s]);
            }
            __syncthreads();
        }
        if (tid == 0)
            g_srcpart[j * 8 + seg] = make_int4(si0[0], si1[0], si2[0], si3[0]);
    }
    {   // zero masks_rot background
        float4* z4 = (float4*)seg3;
        float4 z = make_float4(0.f, 0.f, 0.f, 0.f);
        int n4 = NM * BN * NPIX / 4;
        for (int k = bid * 256 + tid; k < n4; k += G * 256) z4[k] = z;
    }
    {   // resize 128->512 (jax linear, clamped)
        int nR = BN * NPIX / 4;
        for (int idx = bid * 256 + tid; idx < nR; idx += G * 256) {
            int b = idx / (NPIX / 4), r4 = idx % (NPIX / 4);
            int i = r4 >> 7;
            int j0 = (r4 & 127) * 4;
            float fy = (i + 0.5f) * 0.25f - 0.5f;
            fy = fminf(fmaxf(fy, 0.f), 127.f);
            int y0 = (int)fy;
            float wy = fy - (float)y0;
            int y1 = min(y0 + 1, 127);
            const float* p = base + b * 128 * 128;
            const float* r0p = p + y0 * 128;
            const float* r1p = p + y1 * 128;
            float4 o;
            #pragma unroll
            for (int q = 0; q < 4; q++) {
                float fx = (j0 + q + 0.5f) * 0.25f - 0.5f;
                fx = fminf(fmaxf(fx, 0.f), 127.f);
                int x0 = (int)fx;
                float wx = fx - (float)x0;
                int x1 = min(x0 + 1, 127);
                float top = (1.f - wx) * __ldg(r0p + x0) + wx * __ldg(r0p + x1);
                float bot = (1.f - wx) * __ldg(r1p + x0) + wx * __ldg(r1p + x1);
                ((float*)&o)[q] = (1.f - wy) * top + wy * bot;
            }
            ((float4*)seg0)[idx] = o;
        }
    }
    grid.sync();

    // ======== stage 1: warp A (inv translation): seg0 -> bufA ========
    warp_stage(seg0, g_bufA, nullptr, 2 * BN, bid, G, tid);
    grid.sync();

    // ======== stage 2: warp B (inv rotation) on most blocks; mask1 on last 64 ========
    if (bid >= G - 64) {
        int jb = bid - (G - 64);
        int j = jb / BN, b = jb % BN;
        int r0, r1, c0, c1;
        combine_srcbox(j, r0, r1, c0, c1);
        if (r1 >= r0) {
            int a0, a1, b0, b1;
            preimage_px(g_inv + (BN + b) * 6,
                        (float)r0 - 1.f, (float)r1 + 1.f,
                        (float)c0 - 1.f, (float)c1 + 1.f, a0, a1, b0, b1);
            int w0 = max(0, a0 - 2), w1 = min(511, a1 + 2);
            int w2 = max(0, b0 - 2), w3 = min(511, b1 + 2);
            int bh = w1 - w0 + 1, bw = w3 - w2 + 1;
            const float* th = g_inv + (BN + b) * 6;
            float t0 = th[0], t1 = th[1], t2 = th[2], t3 = th[3], t4 = th[4], t5 = th[5];
            const float* s = masks + j * NPIX;
            float* dstm = g_rm2 + (size_t)jb * NPIX;
            for (int t = tid; t < bh * bw; t += 256) {
                int i = w0 + t / bw, jj = w2 + t % bw;
                float X = (float)(2 * jj + 1) / 512.0f - 1.0f;
                float Y = (float)(2 * i + 1) / 512.0f - 1.0f;
                dstm[(i << 9) + jj] = bilin_ro(s, t0 * X + t1 * Y + t2,
                                                  t3 * X + t4 * Y + t5);
            }
        }
    } else {
        warp_stage(g_bufA, g_bufB, nullptr, 1 * BN, bid, G - 64, tid);
    }
    grid.sync();

    // ======== stage 3: warp C (inv shear): bufB -> seg1 & seg2 ========
    warp_stage(g_bufB, seg1, seg2, 0, bid, G, tid);
    grid.sync();

    // ======== stage 4: mask stage2 + threshold + COM (blocks 0..63) ========
    if (bid < NM * BN) {
        int jb = bid, j = jb / BN, b = jb % BN;
        int r0, r1, c0, c1;
        combine_srcbox(j, r0, r1, c0, c1);
        int d0 = 0, e0 = 0, bh = 0, bw = 0;
        if (r1 >= r0) {
            int a0, a1, b0, b1;
            preimage_px(g_inv + (BN + b) * 6,
                        (float)r0 - 1.f, (float)r1 + 1.f,
                        (float)c0 - 1.f, (float)c1 + 1.f, a0, a1, b0, b1);
            int dd0, dd1, ee0, ee1;
            preimage_px(g_inv + b * 6,
                        (float)a0 - 1.f, (float)a1 + 1.f,
                        (float)b0 - 1.f, (float)b1 + 1.f, dd0, dd1, ee0, ee1);
            d0 = max(0, dd0 - 1); int d1 = min(511, dd1 + 1);
            e0 = max(0, ee0 - 1); int e1 = min(511, ee1 + 1);
            bh = d1 - d0 + 1; bw = e1 - e0 + 1;
        }
        int area = bh * bw;
        const float* th = g_inv + b * 6;
        float t0 = th[0], t1 = th[1], t2 = th[2], t3 = th[3], t4 = th[4], t5 = th[5];
        const float* src = g_rm2 + (size_t)jb * NPIX;
        const float* img = seg1 + b * NPIX;
        float* dst = seg3 + (size_t)jb * NPIX;
        float sn = 0.f, sm = 0.f;
        for (int t = tid; t < area; t += 256) {
            int i = d0 + t / bw, jj = e0 + t % bw;
            float X = (float)(2 * jj + 1) / 512.0f - 1.0f;
            float Y = (float)(2 * i + 1) / 512.0f - 1.0f;
            float v = bilin_rw(src, t0 * X + t1 * Y + t2, t3 * X + t4 * Y + t5);
            int g = (i << 9) + jj;
            bool on = (v >= 0.5f);
            dst[g] = on ? 1.0f : 0.0f;
            if (on) { sn += img[g]; sm += 1.0f; }
        }
        sh1[tid] = sn; sh2[tid] = sm;
        __syncthreads();
        for (int s = 128; s > 0; s >>= 1) {
            if (tid < s) { sh1[tid] += sh1[tid + s]; sh2[tid] += sh2[tid + s]; }
            __syncthreads();
        }
        if (tid == 0) sh_thr = (sh1[0] / fmaxf(sh2[0], 1.0f)) * 1.5f;
        __syncthreads();
        float thr = sh_thr;

        float st = 0.f, sx = 0.f, sy = 0.f;
        for (int t = tid; t < area; t += 256) {
            int i = d0 + t / bw, jj = e0 + t % bw;
            int g = (i << 9) + jj;
            if (dst[g] > 0.5f) {
                float nv = img[g];
                if (nv > thr) {
                    st += nv;
                    sx += nv * (float)i;
                    sy += nv * (float)jj;
                }
            }
        }
        sh1[tid] = st; sh2[tid] = sx; sh3[tid] = sy;
        __syncthreads();
        for (int s = 128; s > 0; s >>= 1) {
            if (tid < s) {
                sh1[tid] += sh1[tid + s];
                sh2[tid] += sh2[tid + s];
                sh3[tid] += sh3[tid + s];
            }
            __syncthreads();
        }
        if (tid == 0) {
            g_com[jb * 3 + 0] = sh1[0];
            g_com[jb * 3 + 1] = sh2[0];
            g_com[jb * 3 + 2] = sh3[0];
        }
    }
    grid.sync();

    // ======== stage 5: revise (blocks 0..15, one per batch item) ========
    if (bid < BN) {
        int b = bid;
        float a = __ldg(adj + b);
        float* img = seg2 + b * NPIX;
        float* patch = g_patch + b * PATCH * PATCH;
        const float* th = g_inv + b * 6;
        for (int j = 0; j < NM; j++) {
            if (tid == 0) {
                int o = (j * BN + b) * 3;
                float tot = g_com[o] + 1e-8f;
                float cx = g_com[o + 1] / tot, cy = g_com[o + 2] / tot;
                int x0 = __float2int_rn(cx) - 60;            // round half to even
                int y0 = __float2int_rn(cy) - 60;
                x0 = min(max(x0, 0), UPD - PATCH);           // dynamic_slice clamping
                y0 = min(max(y0, 0), UPD - PATCH);
                sh_xy[0] = x0; sh_xy[1] = y0;
            }
            __syncthreads();
            int x0 = sh_xy[0], y0 = sh_xy[1];
            for (int t = tid; t < PATCH * PATCH; t += 256) {
                int p = t / PATCH, q = t - p * PATCH;
                float v = img[(x0 + p) * UPD + (y0 + q)];
                int dp = p - 60, dq = q - 60;
                if (dp * dp + dq * dq <= 16) v = v / a;
                patch[t] = v;
            }
            __syncthreads();
            for (int t = tid; t < PATCH * PATCH; t += 256) {
                int p = t / PATCH, q = t - p * PATCH;
                float X = (float)(2 * q + 1) / 120.0f - 1.0f;
                float Y = (float)(2 * p + 1) / 120.0f - 1.0f;
                float gx = th[0] * X + th[1] * Y + th[2];
                float gy = th[3] * X + th[4] * Y + th[5];
                float x = ((gx + 1.0f) * 120.0f - 1.0f) * 0.5f;
                float y = ((gy + 1.0f) * 120.0f - 1.0f) * 0.5f;
                float xf = floorf(x), yf = floorf(y);
                int xx0 = (int)xf, yy0 = (int)yf;
                float wx = x - xf, wy = y - yf;
                int xx1 = xx0 + 1, yy1 = yy0 + 1;
                bool xi0 = (xx0 >= 0) && (xx0 < PATCH);
                bool xi1 = (xx1 >= 0) && (xx1 < PATCH);
                bool yi0 = (yy0 >= 0) && (yy0 < PATCH);
                bool yi1 = (yy1 >= 0) && (yy1 < PATCH);
                float v00 = (yi0 && xi0) ? patch[yy0 * PATCH + xx0] : 0.f;
                float v01 = (yi0 && xi1) ? patch[yy0 * PATCH + xx1] : 0.f;
                float v10 = (yi1 && xi0) ? patch[yy1 * PATCH + xx0] : 0.f;
                float v11 = (yi1 && xi1) ? patch[yy1 * PATCH + xx1] : 0.f;
                float v = (1.f - wx) * (1.f - wy) * v00 + wx * (1.f - wy) * v01
                        + (1.f - wx) * wy * v10 + wx * wy * v11;
                img[(x0 + p) * UPD + (y0 + q)] = v;
            }
            __syncthreads();
        }
    }
}

// ---------------- launch ----------------
extern "C" void kernel_launch(void* const* d_in, const int* in_sizes, int n_in,
                              void* d_out, int out_size) {
    const float* base  = (const float*)d_in[0];
    const float* sc    = (const float*)d_in[1];
    const float* ro    = (const float*)d_in[2];
    const float* tr    = (const float*)d_in[3];
    const float* adj   = (const float*)d_in[4];
    const float* masks = (const float*)d_in[5];
    float* out = (float*)d_out;

    // One-time occupancy-based cooperative grid sizing (host queries only;
    // no allocations, no streams, no events).
    static int gridBlocks = 0;
    if (gridBlocks == 0) {
        int dev = 0;
        cudaGetDevice(&dev);
        int sms = 0;
        cudaDeviceGetAttribute(&sms, cudaDevAttrMultiProcessorCount, dev);
        int nb = 0;
        cudaOccupancyMaxActiveBlocksPerMultiprocessor(&nb, (const void*)k_mega, 256, 0);
        if (nb < 1) nb = 1;
        gridBlocks = nb * sms;
        if (gridBlocks < 80) gridBlocks = 80;   // need >= 65 for role splits
    }

    void* args[7] = {
        (void*)&base, (void*)&sc, (void*)&ro, (void*)&tr,
        (void*)&adj, (void*)&masks, (void*)&out
    };
    cudaLaunchCooperativeKernel((const void*)k_mega,
                                dim3(gridBlocks), dim3(256), args, 0, (cudaStream_t)0);
}

// round 14
// speedup vs baseline: 3.0777x; 3.0777x over previous
#include <cuda_runtime.h>
#include <math.h>

#define BN 16
#define UPD 512
#define NPIX (UPD*UPD)
#define PATCH 120
#define NM 4
#define TPB 256

// ---------------- static device scratch (zero-initialized at load) ----------------
__device__ float g_bufA[BN*NPIX];               // pred_trans
__device__ float g_bufB[BN*NPIX];               // pred_rot
__device__ float g_rm2[NM*BN*NPIX];             // mask after g2 sample (zero outside boxes)
__device__ int4  g_srcpart[NM*8];               // per-j partial src bboxes
__device__ float g_com[NM*BN*3];                // per (j,b): tot, sx, sy

// ---------------- helpers ----------------
// 2x3 affine inverse — identical arithmetic order to the old k_inv kernel
__device__ __forceinline__ void inv2x3(const float* __restrict__ m, float* o) {
    float a = m[0], bb = m[1], c = m[2], d = m[3], e = m[4], f = m[5];
    float det = a * e - bb * d;
    float ia = e / det, ib = -bb / det, id = -d / det, ie = a / det;
    o[0] = ia; o[1] = ib; o[2] = -(ia * c + ib * f);
    o[3] = id; o[4] = ie; o[5] = -(id * c + ie * f);
}

__device__ __forceinline__ float bilin_sample(const float* __restrict__ s,
                                              float gx, float gy, int H, int W) {
    // torch grid_sample: bilinear, zero padding, align_corners=False
    float x = ((gx + 1.0f) * (float)W - 1.0f) * 0.5f;
    float y = ((gy + 1.0f) * (float)H - 1.0f) * 0.5f;
    float xf = floorf(x), yf = floorf(y);
    int x0 = (int)xf, y0 = (int)yf;
    float wx = x - xf, wy = y - yf;
    int x1 = x0 + 1, y1 = y0 + 1;
    bool xi0 = (x0 >= 0) && (x0 < W);
    bool xi1 = (x1 >= 0) && (x1 < W);
    bool yi0 = (y0 >= 0) && (y0 < H);
    bool yi1 = (y1 >= 0) && (y1 < H);
    float v00 = 0.f, v01 = 0.f, v10 = 0.f, v11 = 0.f;
    if (yi0) {
        const float* row = s + y0 * W;
        if (xi0) v00 = __ldg(row + x0);
        if (xi1) v01 = __ldg(row + x1);
    }
    if (yi1) {
        const float* row = s + y1 * W;
        if (xi0) v10 = __ldg(row + x0);
        if (xi1) v11 = __ldg(row + x1);
    }
    return (1.f - wx) * (1.f - wy) * v00 + wx * (1.f - wy) * v01
         + (1.f - wx) * wy * v10 + wx * wy * v11;
}

__device__ __forceinline__ void preimage_px(const float* th,
        float ya, float yb, float xa, float xb,
        int& ir0, int& ir1, int& ic0, int& ic1) {
    float gxa = (2.f * xa + 1.f) / 512.f - 1.f, gxb = (2.f * xb + 1.f) / 512.f - 1.f;
    float gya = (2.f * ya + 1.f) / 512.f - 1.f, gyb = (2.f * yb + 1.f) / 512.f - 1.f;
    float det = th[0] * th[4] - th[1] * th[3];
    float Xmin = 1e30f, Xmax = -1e30f, Ymin = 1e30f, Ymax = -1e30f;
    #pragma unroll
    for (int u = 0; u < 4; u++) {
        float gx = (u & 1) ? gxb : gxa;
        float gy = (u & 2) ? gyb : gya;
        float rx = gx - th[2], ry = gy - th[5];
        float X = ( th[4] * rx - th[1] * ry) / det;
        float Y = (-th[3] * rx + th[0] * ry) / det;
        Xmin = fminf(Xmin, X); Xmax = fmaxf(Xmax, X);
        Ymin = fminf(Ymin, Y); Ymax = fmaxf(Ymax, Y);
    }
    float jmin = ((Xmin + 1.f) * 512.f - 1.f) * 0.5f;
    float jmax = ((Xmax + 1.f) * 512.f - 1.f) * 0.5f;
    float imin = ((Ymin + 1.f) * 512.f - 1.f) * 0.5f;
    float imax = ((Ymax + 1.f) * 512.f - 1.f) * 0.5f;
    ir0 = max(0,   (int)floorf(imin) - 1);
    ir1 = min(511, (int)ceilf(imax) + 1);
    ic0 = max(0,   (int)floorf(jmin) - 1);
    ic1 = min(511, (int)ceilf(jmax) + 1);
}

__device__ __forceinline__ void combine_srcbox(int j, int& r0, int& r1, int& c0, int& c1) {
    r0 = 1 << 20; r1 = -1; c0 = 1 << 20; c1 = -1;
    #pragma unroll
    for (int k = 0; k < 8; k++) {
        int4 p = g_srcpart[j * 8 + k];
        r0 = min(r0, p.x); r1 = max(r1, p.y);
        c0 = min(c0, p.z); c1 = max(c1, p.w);
    }
}

// core box1 (pre-dilation) for (j,b): preimage of src bbox through inv(rotation)
__device__ __forceinline__ bool box1_core(int j, const float* ithro,
                                          int& a0, int& a1, int& b0, int& b1) {
    int r0, r1, c0, c1;
    combine_srcbox(j, r0, r1, c0, c1);
    if (r1 < r0) return false;
    preimage_px(ithro, (float)r0 - 1.f, (float)r1 + 1.f,
                (float)c0 - 1.f, (float)c1 + 1.f, a0, a1, b0, b1);
    return true;
}

// ---------------- source mask bbox (partials; side stream) ----------------
__global__ void k_srcbox(const float* __restrict__ masks) {
    int j = blockIdx.y, seg = blockIdx.x;
    const float* m = masks + j * NPIX;
    int base = seg * (NPIX / 8);
    int rmin = 1 << 20, rmax = -1, cmin = 1 << 20, cmax = -1;
    for (int k = threadIdx.x; k < NPIX / 8; k += TPB) {
        int g = base + k;
        if (m[g] != 0.0f) {
            int r = g >> 9, c = g & 511;
            rmin = min(rmin, r); rmax = max(rmax, r);
            cmin = min(cmin, c); cmax = max(cmax, c);
        }
    }
    __shared__ int s0[TPB], s1[TPB], s2[TPB], s3[TPB];
    s0[threadIdx.x] = rmin; s1[threadIdx.x] = rmax;
    s2[threadIdx.x] = cmin; s3[threadIdx.x] = cmax;
    __syncthreads();
    for (int s = TPB / 2; s > 0; s >>= 1) {
        if (threadIdx.x < s) {
            s0[threadIdx.x] = min(s0[threadIdx.x], s0[threadIdx.x + s]);
            s1[threadIdx.x] = max(s1[threadIdx.x], s1[threadIdx.x + s]);
            s2[threadIdx.x] = min(s2[threadIdx.x], s2[threadIdx.x + s]);
            s3[threadIdx.x] = max(s3[threadIdx.x], s3[threadIdx.x + s]);
        }
        __syncthreads();
    }
    if (threadIdx.x == 0)
        g_srcpart[j * 8 + seg] = make_int4(s0[0], s1[0], s2[0], s3[0]);
}

// ---------------- K1: jax.image.resize linear, 4 outputs/thread ----------------
__global__ void k_resize4(const float* __restrict__ base, float* __restrict__ out) {
    int idx = blockIdx.x * blockDim.x + threadIdx.x;
    if (idx >= BN * NPIX / 4) return;
    int b = idx / (NPIX / 4), r4 = idx - b * (NPIX / 4);
    int i = r4 >> 7;
    int j0 = (r4 & 127) * 4;
    float fy = (i + 0.5f) * 0.25f - 0.5f;
    fy = fminf(fmaxf(fy, 0.f), 127.f);
    int y0 = (int)fy;
    float wy = fy - (float)y0;
    int y1 = min(y0 + 1, 127);
    const float* p = base + b * 128 * 128;
    const float* r0 = p + y0 * 128;
    const float* r1 = p + y1 * 128;
    float4 o;
    #pragma unroll
    for (int q = 0; q < 4; q++) {
        float fx = (j0 + q + 0.5f) * 0.25f - 0.5f;
        fx = fminf(fmaxf(fx, 0.f), 127.f);
        int x0 = (int)fx;
        float wx = fx - (float)x0;
        int x1 = min(x0 + 1, 127);
        float top = (1.f - wx) * __ldg(r0 + x0) + wx * __ldg(r0 + x1);
        float bot = (1.f - wx) * __ldg(r1 + x0) + wx * __ldg(r1 + x1);
        ((float*)&o)[q] = (1.f - wy) * top + wy * bot;
    }
    ((float4*)out)[idx] = o;
}

// ---------------- image warp, square 32x32 tile, 4 rows/thread ----------------
// Inverse theta computed in-kernel from the raw forward theta (no k_inv node).
__global__ void k_warp4sq(const float* __restrict__ src, float* __restrict__ dst,
                          float* __restrict__ dst2, const float* __restrict__ theta) {
    int b = blockIdx.z;
    float th[6];
    inv2x3(theta + b * 6, th);
    int i0 = blockIdx.y * 32 + threadIdx.y;
    int j  = blockIdx.x * 32 + threadIdx.x;
    float t0 = th[0], t1 = th[1], t2 = th[2], t3 = th[3], t4 = th[4], t5 = th[5];
    float X = (float)(2 * j + 1) / 512.0f - 1.0f;
    float gxX = t0 * X + t2;
    float gyX = t3 * X + t5;
    const float* s = src + b * NPIX;
    float v[4];
    #pragma unroll
    for (int q = 0; q < 4; q++) {
        int i = i0 + q * 8;
        float Y = (float)(2 * i + 1) / 512.0f - 1.0f;
        v[q] = bilin_sample(s, gxX + t1 * Y, gyX + t4 * Y, UPD, UPD);
    }
    int base_idx = b * NPIX + (i0 << 9) + j;
    #pragma unroll
    for (int q = 0; q < 4; q++) {
        dst[base_idx + (q << 12)] = v[q];
        if (dst2) dst2[base_idx + (q << 12)] = v[q];
    }
}

// ---------------- mask stage 1 (box-restricted, side stream) ----------------
// Box computed in-block from g_srcpart + inline inverse (no k_boxes node).
__global__ void k_mask1(const float* __restrict__ masks, const float* __restrict__ ro) {
    int jb = blockIdx.y;
    int j = jb / BN, b = jb % BN;
    float th[6];
    inv2x3(ro + b * 6, th);
    int a0, a1, b0, b1;
    if (!box1_core(j, th, a0, a1, b0, b1)) return;
    int w0 = max(0, a0 - 2), w1 = min(511, a1 + 2);
    int w2 = max(0, b0 - 2), w3 = min(511, b1 + 2);
    int bh = w1 - w0 + 1, bw = w3 - w2 + 1;
    int area = bh * bw;
    float t0 = th[0], t1 = th[1], t2 = th[2], t3 = th[3], t4 = th[4], t5 = th[5];
    const float* s = masks + j * NPIX;
    float* dst = g_rm2 + (size_t)jb * NPIX;
    for (int t = blockIdx.x * TPB + threadIdx.x; t < area; t += 8 * TPB) {
        int i = w0 + t / bw, jj = w2 + t % bw;
        float X = (float)(2 * jj + 1) / 512.0f - 1.0f;
        float Y = (float)(2 * i + 1) / 512.0f - 1.0f;
        dst[(i << 9) + jj] = bilin_sample(s, t0 * X + t1 * Y + t2,
                                             t3 * X + t4 * Y + t5, UPD, UPD);
    }
}

// ---------------- FUSED mask stage 2 + threshold + COM: one block per (j,b) ----------------
__global__ void k_mask23(const float* __restrict__ img_all, float* __restrict__ mrot,
                         const float* __restrict__ sc, const float* __restrict__ ro) {
    int jb = blockIdx.x;
    int j = jb / BN, b = jb % BN;
    int tid = threadIdx.x;
    const int NT = 1024;
    __shared__ float sh1[NT], sh2[NT], sh3[NT];
    __shared__ float sh_thr;

    float thro[6], thsc[6];
    inv2x3(ro + b * 6, thro);
    inv2x3(sc + b * 6, thsc);

    // box2: preimage of core box1 through inv(shear), dilated by 1 (as k_boxes)
    int d0 = 0, e0 = 0, bh = 0, bw = 0;
    {
        int a0, a1, b0, b1;
        if (box1_core(j, thro, a0, a1, b0, b1)) {
            int dd0, dd1, ee0, ee1;
            preimage_px(thsc, (float)a0 - 1.f, (float)a1 + 1.f,
                        (float)b0 - 1.f, (float)b1 + 1.f, dd0, dd1, ee0, ee1);
            d0 = max(0, dd0 - 1); int d1 = min(511, dd1 + 1);
            e0 = max(0, ee0 - 1); int e1 = min(511, ee1 + 1);
            bh = d1 - d0 + 1; bw = e1 - e0 + 1;
        }
    }
    int area = bh * bw;
    float t0 = thsc[0], t1 = thsc[1], t2 = thsc[2], t3 = thsc[3], t4 = thsc[4], t5 = thsc[5];
    const float* src = g_rm2 + (size_t)jb * NPIX;
    const float* img = img_all + b * NPIX;
    float* dst = mrot + (size_t)jb * NPIX;
    float sn = 0.f, sm = 0.f;
    for (int t = tid; t < area; t += NT) {
        int i = d0 + t / bw, jj = e0 + t % bw;
        float X = (float)(2 * jj + 1) / 512.0f - 1.0f;
        float Y = (float)(2 * i + 1) / 512.0f - 1.0f;
        float v = bilin_sample(src, t0 * X + t1 * Y + t2, t3 * X + t4 * Y + t5, UPD, UPD);
        int g = (i << 9) + jj;
        bool on = (v >= 0.5f);
        dst[g] = on ? 1.0f : 0.0f;
        if (on) { sn += img[g]; sm += 1.0f; }
    }
    sh1[tid] = sn; sh2[tid] = sm;
    __syncthreads();
    for (int s = NT / 2; s > 0; s >>= 1) {
        if (tid < s) { sh1[tid] += sh1[tid + s]; sh2[tid] += sh2[tid + s]; }
        __syncthreads();
    }
    if (tid == 0) sh_thr = (sh1[0] / fmaxf(sh2[0], 1.0f)) * 1.5f;
    __syncthreads();
    float thr = sh_thr;

    float st = 0.f, sx = 0.f, sy = 0.f;
    for (int t = tid; t < area; t += NT) {
        int i = d0 + t / bw, jj = e0 + t % bw;
        int g = (i << 9) + jj;
        if (dst[g] > 0.5f) {
            float nv = img[g];
            if (nv > thr) {
                st += nv;
                sx += nv * (float)i;
                sy += nv * (float)jj;
            }
        }
    }
    sh1[tid] = st; sh2[tid] = sx; sh3[tid] = sy;
    __syncthreads();
    for (int s = NT / 2; s > 0; s >>= 1) {
        if (tid < s) {
            sh1[tid] += sh1[tid + s];
            sh2[tid] += sh2[tid + s];
            sh3[tid] += sh3[tid + s];
        }
        __syncthreads();
    }
    if (tid == 0) {
        g_com[jb * 3 + 0] = sh1[0];
        g_com[jb * 3 + 1] = sh2[0];
        g_com[jb * 3 + 2] = sh3[0];
    }
}

// ---------------- revise: one block per batch item; patch in dynamic smem ----------------
__global__ void k_revise(float* __restrict__ rev, const float* __restrict__ adj,
                         const float* __restrict__ sc) {
    extern __shared__ float patch[];   // PATCH*PATCH floats = 57.6KB
    int b = blockIdx.x;
    int tid = threadIdx.x;
    float a = adj[b];
    float* img = rev + b * NPIX;
    float th[6];
    inv2x3(sc + b * 6, th);
    __shared__ int sh_xy[2];
    for (int j = 0; j < NM; j++) {
        if (tid == 0) {
            int o = (j * BN + b) * 3;
            float tot = g_com[o] + 1e-8f;
            float cx = g_com[o + 1] / tot, cy = g_com[o + 2] / tot;
            int x0 = __float2int_rn(cx) - 60;            // round half to even
            int y0 = __float2int_rn(cy) - 60;
            x0 = min(max(x0, 0), UPD - PATCH);           // dynamic_slice clamping
            y0 = min(max(y0, 0), UPD - PATCH);
            sh_xy[0] = x0; sh_xy[1] = y0;
        }
        __syncthreads();
        int x0 = sh_xy[0], y0 = sh_xy[1];
        for (int t = tid; t < PATCH * PATCH; t += blockDim.x) {
            int p = t / PATCH, q = t - p * PATCH;
            float v = img[(x0 + p) * UPD + (y0 + q)];
            int dp = p - 60, dq = q - 60;
            if (dp * dp + dq * dq <= 16) v = v / a;
            patch[t] = v;
        }
        __syncthreads();
        for (int t = tid; t < PATCH * PATCH; t += blockDim.x) {
            int p = t / PATCH, q = t - p * PATCH;
            float X = (float)(2 * q + 1) / 120.0f - 1.0f;
            float Y = (float)(2 * p + 1) / 120.0f - 1.0f;
            float gx = th[0] * X + th[1] * Y + th[2];
            float gy = th[3] * X + th[4] * Y + th[5];
            float x = ((gx + 1.0f) * 120.0f - 1.0f) * 0.5f;
            float y = ((gy + 1.0f) * 120.0f - 1.0f) * 0.5f;
            float xf = floorf(x), yf = floorf(y);
            int xx0 = (int)xf, yy0 = (int)yf;
            float wx = x - xf, wy = y - yf;
            int xx1 = xx0 + 1, yy1 = yy0 + 1;
            bool xi0 = (xx0 >= 0) && (xx0 < PATCH);
            bool xi1 = (xx1 >= 0) && (xx1 < PATCH);
            bool yi0 = (yy0 >= 0) && (yy0 < PATCH);
            bool yi1 = (yy1 >= 0) && (yy1 < PATCH);
            float v00 = (yi0 && xi0) ? patch[yy0 * PATCH + xx0] : 0.f;
            float v01 = (yi0 && xi1) ? patch[yy0 * PATCH + xx1] : 0.f;
            float v10 = (yi1 && xi0) ? patch[yy1 * PATCH + xx0] : 0.f;
            float v11 = (yi1 && xi1) ? patch[yy1 * PATCH + xx1] : 0.f;
            float v = (1.f - wx) * (1.f - wy) * v00 + wx * (1.f - wy) * v01
                    + (1.f - wx) * wy * v10 + wx * wy * v11;
            img[(x0 + p) * UPD + (y0 + q)] = v;
        }
        __syncthreads();
    }
}

// ---------------- launch ----------------
extern "C" void kernel_launch(void* const* d_in, const int* in_sizes, int n_in,
                              void* d_out, int out_size) {
    const float* base  = (const float*)d_in[0];
    const float* sc    = (const float*)d_in[1];
    const float* ro    = (const float*)d_in[2];
    const float* tr    = (const float*)d_in[3];
    const float* adj   = (const float*)d_in[4];
    const float* masks = (const float*)d_in[5];
    float* out = (float*)d_out;
    float* seg0 = out;                           // base_inp
    float* seg1 = out + (size_t)BN * NPIX;       // pred_input
    float* seg2 = out + (size_t)2 * BN * NPIX;   // pred_revise
    float* seg3 = out + (size_t)3 * BN * NPIX;   // masks_rot

    float *bufA, *bufB;
    cudaGetSymbolAddress((void**)&bufA, g_bufA);
    cudaGetSymbolAddress((void**)&bufB, g_bufB);

    // One-time resources (created on the uncaptured correctness call; reused
    // during capture — proven-clean 1-stream/2-event configuration).
    static cudaStream_t s1 = nullptr;
    static cudaEvent_t evRoot, evS1;
    static bool init_done = false;
    if (!init_done) {
        cudaFuncSetAttribute(k_revise, cudaFuncAttributeMaxDynamicSharedMemorySize,
                             PATCH * PATCH * (int)sizeof(float));
        cudaStreamCreateWithFlags(&s1, cudaStreamNonBlocking);
        cudaEventCreateWithFlags(&evRoot, cudaEventDisableTiming);
        cudaEventCreateWithFlags(&evS1, cudaEventDisableTiming);
        init_done = true;
    }

    int nblk_img4 = (BN * NPIX / 4 + TPB - 1) / TPB;
    dim3 wgrid(16, 16, BN), wblk(32, 8);

    // fork: side branch is fully independent of the main chain now
    cudaEventRecord(evRoot, 0);
    cudaStreamWaitEvent(s1, evRoot, 0);

    // side branch s1: memset + srcbox + mask1 (boxes computed in-block)
    cudaMemsetAsync(seg3, 0, (size_t)NM * BN * NPIX * sizeof(float), s1);
    k_srcbox<<<dim3(8, NM), TPB, 0, s1>>>(masks);
    k_mask1<<<dim3(8, NM * BN), TPB, 0, s1>>>(masks, ro);
    cudaEventRecord(evS1, s1);

    // main chain: resize -> warpA -> warpB -> warpC -> (join) mask23 -> revise
    k_resize4<<<nblk_img4, TPB>>>(base, seg0);
    k_warp4sq<<<wgrid, wblk>>>(seg0, bufA, nullptr, tr);    // inv(translation)
    k_warp4sq<<<wgrid, wblk>>>(bufA, bufB, nullptr, ro);    // inv(rotation)
    k_warp4sq<<<wgrid, wblk>>>(bufB, seg1, seg2, sc);       // inv(shear)

    cudaStreamWaitEvent(0, evS1, 0);
    k_mask23<<<NM * BN, 1024>>>(seg1, seg3, sc, ro);
    k_revise<<<BN, 1024, PATCH * PATCH * sizeof(float)>>>(seg2, adj, sc);
}

// round 15
// speedup vs baseline: 3.1776x; 1.0325x over previous
#include <cuda_runtime.h>
#include <math.h>

#define BN 16
#define UPD 512
#define NPIX (UPD*UPD)
#define PATCH 120
#define NM 4
#define TPB 256

// ---------------- static device scratch (zero-initialized at load) ----------------
__device__ float g_bufA[BN*NPIX];               // pred_trans
__device__ float g_bufB[BN*NPIX];               // pred_rot
__device__ float g_rm2[NM*BN*NPIX];             // mask after g2 sample (zero outside boxes)
__device__ int4  g_srcpart[NM*8];               // per-j partial src bboxes
__device__ float g_com[NM*BN*3];                // per (j,b): tot, sx, sy

// ---------------- helpers ----------------
// 2x3 affine inverse — identical arithmetic order to the original k_inv kernel
__device__ __forceinline__ void inv2x3(const float* __restrict__ m, float* o) {
    float a = m[0], bb = m[1], c = m[2], d = m[3], e = m[4], f = m[5];
    float det = a * e - bb * d;
    float ia = e / det, ib = -bb / det, id = -d / det, ie = a / det;
    o[0] = ia; o[1] = ib; o[2] = -(ia * c + ib * f);
    o[3] = id; o[4] = ie; o[5] = -(id * c + ie * f);
}

__device__ __forceinline__ float bilin_sample(const float* __restrict__ s,
                                              float gx, float gy, int H, int W) {
    // torch grid_sample: bilinear, zero padding, align_corners=False
    float x = ((gx + 1.0f) * (float)W - 1.0f) * 0.5f;
    float y = ((gy + 1.0f) * (float)H - 1.0f) * 0.5f;
    float xf = floorf(x), yf = floorf(y);
    int x0 = (int)xf, y0 = (int)yf;
    float wx = x - xf, wy = y - yf;
    int x1 = x0 + 1, y1 = y0 + 1;
    bool xi0 = (x0 >= 0) && (x0 < W);
    bool xi1 = (x1 >= 0) && (x1 < W);
    bool yi0 = (y0 >= 0) && (y0 < H);
    bool yi1 = (y1 >= 0) && (y1 < H);
    float v00 = 0.f, v01 = 0.f, v10 = 0.f, v11 = 0.f;
    if (yi0) {
        const float* row = s + y0 * W;
        if (xi0) v00 = __ldg(row + x0);
        if (xi1) v01 = __ldg(row + x1);
    }
    if (yi1) {
        const float* row = s + y1 * W;
        if (xi0) v10 = __ldg(row + x0);
        if (xi1) v11 = __ldg(row + x1);
    }
    return (1.f - wx) * (1.f - wy) * v00 + wx * (1.f - wy) * v01
         + (1.f - wx) * wy * v10 + wx * wy * v11;
}

__device__ __forceinline__ void preimage_px(const float* th,
        float ya, float yb, float xa, float xb,
        int& ir0, int& ir1, int& ic0, int& ic1) {
    float gxa = (2.f * xa + 1.f) / 512.f - 1.f, gxb = (2.f * xb + 1.f) / 512.f - 1.f;
    float gya = (2.f * ya + 1.f) / 512.f - 1.f, gyb = (2.f * yb + 1.f) / 512.f - 1.f;
    float det = th[0] * th[4] - th[1] * th[3];
    float Xmin = 1e30f, Xmax = -1e30f, Ymin = 1e30f, Ymax = -1e30f;
    #pragma unroll
    for (int u = 0; u < 4; u++) {
        float gx = (u & 1) ? gxb : gxa;
        float gy = (u & 2) ? gyb : gya;
        float rx = gx - th[2], ry = gy - th[5];
        float X = ( th[4] * rx - th[1] * ry) / det;
        float Y = (-th[3] * rx + th[0] * ry) / det;
        Xmin = fminf(Xmin, X); Xmax = fmaxf(Xmax, X);
        Ymin = fminf(Ymin, Y); Ymax = fmaxf(Ymax, Y);
    }
    float jmin = ((Xmin + 1.f) * 512.f - 1.f) * 0.5f;
    float jmax = ((Xmax + 1.f) * 512.f - 1.f) * 0.5f;
    float imin = ((Ymin + 1.f) * 512.f - 1.f) * 0.5f;
    float imax = ((Ymax + 1.f) * 512.f - 1.f) * 0.5f;
    ir0 = max(0,   (int)floorf(imin) - 1);
    ir1 = min(511, (int)ceilf(imax) + 1);
    ic0 = max(0,   (int)floorf(jmin) - 1);
    ic1 = min(511, (int)ceilf(jmax) + 1);
}

__device__ __forceinline__ void combine_srcbox(int j, int& r0, int& r1, int& c0, int& c1) {
    r0 = 1 << 20; r1 = -1; c0 = 1 << 20; c1 = -1;
    #pragma unroll
    for (int k = 0; k < 8; k++) {
        int4 p = g_srcpart[j * 8 + k];
        r0 = min(r0, p.x); r1 = max(r1, p.y);
        c0 = min(c0, p.z); c1 = max(c1, p.w);
    }
}

// core box1 (pre-dilation) for (j,b): preimage of src bbox through inv(rotation)
__device__ __forceinline__ bool box1_core(int j, const float* ithro,
                                          int& a0, int& a1, int& b0, int& b1) {
    int r0, r1, c0, c1;
    combine_srcbox(j, r0, r1, c0, c1);
    if (r1 < r0) return false;
    preimage_px(ithro, (float)r0 - 1.f, (float)r1 + 1.f,
                (float)c0 - 1.f, (float)c1 + 1.f, a0, a1, b0, b1);
    return true;
}

// ---------------- source mask bbox (partials; side stream) ----------------
__global__ void k_srcbox(const float* __restrict__ masks) {
    int j = blockIdx.y, seg = blockIdx.x;
    const float* m = masks + j * NPIX;
    int base = seg * (NPIX / 8);
    int rmin = 1 << 20, rmax = -1, cmin = 1 << 20, cmax = -1;
    for (int k = threadIdx.x; k < NPIX / 8; k += TPB) {
        int g = base + k;
        if (m[g] != 0.0f) {
            int r = g >> 9, c = g & 511;
            rmin = min(rmin, r); rmax = max(rmax, r);
            cmin = min(cmin, c); cmax = max(cmax, c);
        }
    }
    __shared__ int s0[TPB], s1[TPB], s2[TPB], s3[TPB];
    s0[threadIdx.x] = rmin; s1[threadIdx.x] = rmax;
    s2[threadIdx.x] = cmin; s3[threadIdx.x] = cmax;
    __syncthreads();
    for (int s = TPB / 2; s > 0; s >>= 1) {
        if (threadIdx.x < s) {
            s0[threadIdx.x] = min(s0[threadIdx.x], s0[threadIdx.x + s]);
            s1[threadIdx.x] = max(s1[threadIdx.x], s1[threadIdx.x + s]);
            s2[threadIdx.x] = min(s2[threadIdx.x], s2[threadIdx.x + s]);
            s3[threadIdx.x] = max(s3[threadIdx.x], s3[threadIdx.x + s]);
        }
        __syncthreads();
    }
    if (threadIdx.x == 0)
        g_srcpart[j * 8 + seg] = make_int4(s0[0], s1[0], s2[0], s3[0]);
}

// ---------------- K1: jax.image.resize linear, 4 outputs/thread ----------------
__global__ void k_resize4(const float* __restrict__ base, float* __restrict__ out) {
    int idx = blockIdx.x * blockDim.x + threadIdx.x;
    if (idx >= BN * NPIX / 4) return;
    int b = idx / (NPIX / 4), r4 = idx - b * (NPIX / 4);
    int i = r4 >> 7;
    int j0 = (r4 & 127) * 4;
    float fy = (i + 0.5f) * 0.25f - 0.5f;
    fy = fminf(fmaxf(fy, 0.f), 127.f);
    int y0 = (int)fy;
    float wy = fy - (float)y0;
    int y1 = min(y0 + 1, 127);
    const float* p = base + b * 128 * 128;
    const float* r0 = p + y0 * 128;
    const float* r1 = p + y1 * 128;
    float4 o;
    #pragma unroll
    for (int q = 0; q < 4; q++) {
        float fx = (j0 + q + 0.5f) * 0.25f - 0.5f;
        fx = fminf(fmaxf(fx, 0.f), 127.f);
        int x0 = (int)fx;
        float wx = fx - (float)x0;
        int x1 = min(x0 + 1, 127);
        float top = (1.f - wx) * __ldg(r0 + x0) + wx * __ldg(r0 + x1);
        float bot = (1.f - wx) * __ldg(r1 + x0) + wx * __ldg(r1 + x1);
        ((float*)&o)[q] = (1.f - wy) * top + wy * bot;
    }
    ((float4*)out)[idx] = o;
}

// ---------------- image warp, square 32x32 tile, 4 rows/thread ----------------
// Inverse theta computed ONCE PER BLOCK (thread 0 -> smem broadcast): keeps the
// k_inv node deleted without paying per-thread divisions (round-14 regression).
__global__ void k_warp4sq(const float* __restrict__ src, float* __restrict__ dst,
                          float* __restrict__ dst2, const float* __restrict__ theta) {
    __shared__ float th[6];
    int b = blockIdx.z;
    if (threadIdx.x == 0 && threadIdx.y == 0)
        inv2x3(theta + b * 6, th);
    __syncthreads();
    int i0 = blockIdx.y * 32 + threadIdx.y;
    int j  = blockIdx.x * 32 + threadIdx.x;
    float t0 = th[0], t1 = th[1], t2 = th[2], t3 = th[3], t4 = th[4], t5 = th[5];
    float X = (float)(2 * j + 1) / 512.0f - 1.0f;
    float gxX = t0 * X + t2;
    float gyX = t3 * X + t5;
    const float* s = src + b * NPIX;
    float v[4];
    #pragma unroll
    for (int q = 0; q < 4; q++) {
        int i = i0 + q * 8;
        float Y = (float)(2 * i + 1) / 512.0f - 1.0f;
        v[q] = bilin_sample(s, gxX + t1 * Y, gyX + t4 * Y, UPD, UPD);
    }
    int base_idx = b * NPIX + (i0 << 9) + j;
    #pragma unroll
    for (int q = 0; q < 4; q++) {
        dst[base_idx + (q << 12)] = v[q];
        if (dst2) dst2[base_idx + (q << 12)] = v[q];
    }
}

// ---------------- mask stage 1 (box-restricted, side stream) ----------------
// Inverse + box computed once per block (thread 0 -> smem broadcast).
__global__ void k_mask1(const float* __restrict__ masks, const float* __restrict__ ro) {
    __shared__ float th[6];
    __shared__ int sbx[4];     // w0, w2, bh, bw
    int jb = blockIdx.y;
    int j = jb / BN, b = jb % BN;
    if (threadIdx.x == 0) {
        inv2x3(ro + b * 6, th);
        int a0, a1, b0, b1;
        if (box1_core(j, th, a0, a1, b0, b1)) {
            int w0 = max(0, a0 - 2), w1 = min(511, a1 + 2);
            int w2 = max(0, b0 - 2), w3 = min(511, b1 + 2);
            sbx[0] = w0; sbx[1] = w2;
            sbx[2] = w1 - w0 + 1; sbx[3] = w3 - w2 + 1;
        } else {
            sbx[0] = sbx[1] = sbx[2] = sbx[3] = 0;
        }
    }
    __syncthreads();
    int w0 = sbx[0], w2 = sbx[1], bh = sbx[2], bw = sbx[3];
    int area = bh * bw;
    float t0 = th[0], t1 = th[1], t2 = th[2], t3 = th[3], t4 = th[4], t5 = th[5];
    const float* s = masks + j * NPIX;
    float* dst = g_rm2 + (size_t)jb * NPIX;
    for (int t = blockIdx.x * TPB + threadIdx.x; t < area; t += 8 * TPB) {
        int i = w0 + t / bw, jj = w2 + t % bw;
        float X = (float)(2 * jj + 1) / 512.0f - 1.0f;
        float Y = (float)(2 * i + 1) / 512.0f - 1.0f;
        dst[(i << 9) + jj] = bilin_sample(s, t0 * X + t1 * Y + t2,
                                             t3 * X + t4 * Y + t5, UPD, UPD);
    }
}

// ---------------- FUSED mask stage 2 + threshold + COM: one block per (j,b) ----------------
__global__ void k_mask23(const float* __restrict__ img_all, float* __restrict__ mrot,
                         const float* __restrict__ sc, const float* __restrict__ ro) {
    int jb = blockIdx.x;
    int j = jb / BN, b = jb % BN;
    int tid = threadIdx.x;
    const int NT = 1024;
    __shared__ float sh1[NT], sh2[NT], sh3[NT];
    __shared__ float sh_thr;
    __shared__ float th[6];
    __shared__ int sbx[4];     // d0, e0, bh, bw

    if (tid == 0) {
        float thro[6];
        inv2x3(ro + b * 6, thro);
        inv2x3(sc + b * 6, th);
        int a0, a1, b0, b1;
        if (box1_core(j, thro, a0, a1, b0, b1)) {
            int dd0, dd1, ee0, ee1;
            preimage_px(th, (float)a0 - 1.f, (float)a1 + 1.f,
                        (float)b0 - 1.f, (float)b1 + 1.f, dd0, dd1, ee0, ee1);
            int d0 = max(0, dd0 - 1), d1 = min(511, dd1 + 1);
            int e0 = max(0, ee0 - 1), e1 = min(511, ee1 + 1);
            sbx[0] = d0; sbx[1] = e0;
            sbx[2] = d1 - d0 + 1; sbx[3] = e1 - e0 + 1;
        } else {
            sbx[0] = sbx[1] = sbx[2] = sbx[3] = 0;
        }
    }
    __syncthreads();
    int d0 = sbx[0], e0 = sbx[1], bh = sbx[2], bw = sbx[3];
    int area = bh * bw;
    float t0 = th[0], t1 = th[1], t2 = th[2], t3 = th[3], t4 = th[4], t5 = th[5];
    const float* src = g_rm2 + (size_t)jb * NPIX;
    const float* img = img_all + b * NPIX;
    float* dst = mrot + (size_t)jb * NPIX;
    float sn = 0.f, sm = 0.f;
    for (int t = tid; t < area; t += NT) {
        int i = d0 + t / bw, jj = e0 + t % bw;
        float X = (float)(2 * jj + 1) / 512.0f - 1.0f;
        float Y = (float)(2 * i + 1) / 512.0f - 1.0f;
        float v = bilin_sample(src, t0 * X + t1 * Y + t2, t3 * X + t4 * Y + t5, UPD, UPD);
        int g = (i << 9) + jj;
        bool on = (v >= 0.5f);
        dst[g] = on ? 1.0f : 0.0f;
        if (on) { sn += img[g]; sm += 1.0f; }
    }
    sh1[tid] = sn; sh2[tid] = sm;
    __syncthreads();
    for (int s = NT / 2; s > 0; s >>= 1) {
        if (tid < s) { sh1[tid] += sh1[tid + s]; sh2[tid] += sh2[tid + s]; }
        __syncthreads();
    }
    if (tid == 0) sh_thr = (sh1[0] / fmaxf(sh2[0], 1.0f)) * 1.5f;
    __syncthreads();
    float thr = sh_thr;

    float st = 0.f, sx = 0.f, sy = 0.f;
    for (int t = tid; t < area; t += NT) {
        int i = d0 + t / bw, jj = e0 + t % bw;
        int g = (i << 9) + jj;
        if (dst[g] > 0.5f) {
            float nv = img[g];
            if (nv > thr) {
                st += nv;
                sx += nv * (float)i;
                sy += nv * (float)jj;
            }
        }
    }
    sh1[tid] = st; sh2[tid] = sx; sh3[tid] = sy;
    __syncthreads();
    for (int s = NT / 2; s > 0; s >>= 1) {
        if (tid < s) {
            sh1[tid] += sh1[tid + s];
            sh2[tid] += sh2[tid + s];
            sh3[tid] += sh3[tid + s];
        }
        __syncthreads();
    }
    if (tid == 0) {
        g_com[jb * 3 + 0] = sh1[0];
        g_com[jb * 3 + 1] = sh2[0];
        g_com[jb * 3 + 2] = sh3[0];
    }
}

// ---------------- revise: one block per batch item; patch in dynamic smem ----------------
__global__ void k_revise(float* __restrict__ rev, const float* __restrict__ adj,
                         const float* __restrict__ sc) {
    extern __shared__ float patch[];   // PATCH*PATCH floats = 57.6KB
    __shared__ float th[6];
    __shared__ int sh_xy[2];
    int b = blockIdx.x;
    int tid = threadIdx.x;
    float a = adj[b];
    float* img = rev + b * NPIX;
    if (tid == 0) inv2x3(sc + b * 6, th);
    __syncthreads();
    for (int j = 0; j < NM; j++) {
        if (tid == 0) {
            int o = (j * BN + b) * 3;
            float tot = g_com[o] + 1e-8f;
            float cx = g_com[o + 1] / tot, cy = g_com[o + 2] / tot;
            int x0 = __float2int_rn(cx) - 60;            // round half to even
            int y0 = __float2int_rn(cy) - 60;
            x0 = min(max(x0, 0), UPD - PATCH);           // dynamic_slice clamping
            y0 = min(max(y0, 0), UPD - PATCH);
            sh_xy[0] = x0; sh_xy[1] = y0;
        }
        __syncthreads();
        int x0 = sh_xy[0], y0 = sh_xy[1];
        for (int t = tid; t < PATCH * PATCH; t += blockDim.x) {
            int p = t / PATCH, q = t - p * PATCH;
            float v = img[(x0 + p) * UPD + (y0 + q)];
            int dp = p - 60, dq = q - 60;
            if (dp * dp + dq * dq <= 16) v = v / a;
            patch[t] = v;
        }
        __syncthreads();
        for (int t = tid; t < PATCH * PATCH; t += blockDim.x) {
            int p = t / PATCH, q = t - p * PATCH;
            float X = (float)(2 * q + 1) / 120.0f - 1.0f;
            float Y = (float)(2 * p + 1) / 120.0f - 1.0f;
            float gx = th[0] * X + th[1] * Y + th[2];
            float gy = th[3] * X + th[4] * Y + th[5];
            float x = ((gx + 1.0f) * 120.0f - 1.0f) * 0.5f;
            float y = ((gy + 1.0f) * 120.0f - 1.0f) * 0.5f;
            float xf = floorf(x), yf = floorf(y);
            int xx0 = (int)xf, yy0 = (int)yf;
            float wx = x - xf, wy = y - yf;
            int xx1 = xx0 + 1, yy1 = yy0 + 1;
            bool xi0 = (xx0 >= 0) && (xx0 < PATCH);
            bool xi1 = (xx1 >= 0) && (xx1 < PATCH);
            bool yi0 = (yy0 >= 0) && (yy0 < PATCH);
            bool yi1 = (yy1 >= 0) && (yy1 < PATCH);
            float v00 = (yi0 && xi0) ? patch[yy0 * PATCH + xx0] : 0.f;
            float v01 = (yi0 && xi1) ? patch[yy0 * PATCH + xx1] : 0.f;
            float v10 = (yi1 && xi0) ? patch[yy1 * PATCH + xx0] : 0.f;
            float v11 = (yi1 && xi1) ? patch[yy1 * PATCH + xx1] : 0.f;
            float v = (1.f - wx) * (1.f - wy) * v00 + wx * (1.f - wy) * v01
                    + (1.f - wx) * wy * v10 + wx * wy * v11;
            img[(x0 + p) * UPD + (y0 + q)] = v;
        }
        __syncthreads();
    }
}

// ---------------- launch ----------------
extern "C" void kernel_launch(void* const* d_in, const int* in_sizes, int n_in,
                              void* d_out, int out_size) {
    const float* base  = (const float*)d_in[0];
    const float* sc    = (const float*)d_in[1];
    const float* ro    = (const float*)d_in[2];
    const float* tr    = (const float*)d_in[3];
    const float* adj   = (const float*)d_in[4];
    const float* masks = (const float*)d_in[5];
    float* out = (float*)d_out;
    float* seg0 = out;                           // base_inp
    float* seg1 = out + (size_t)BN * NPIX;       // pred_input
    float* seg2 = out + (size_t)2 * BN * NPIX;   // pred_revise
    float* seg3 = out + (size_t)3 * BN * NPIX;   // masks_rot

    float *bufA, *bufB;
    cudaGetSymbolAddress((void**)&bufA, g_bufA);
    cudaGetSymbolAddress((void**)&bufB, g_bufB);

    // One-time resources (created on the uncaptured correctness call; reused
    // during capture — proven-clean 1-stream/2-event configuration).
    static cudaStream_t s1 = nullptr;
    static cudaEvent_t evRoot, evS1;
    static bool init_done = false;
    if (!init_done) {
        cudaFuncSetAttribute(k_revise, cudaFuncAttributeMaxDynamicSharedMemorySize,
                             PATCH * PATCH * (int)sizeof(float));
        cudaStreamCreateWithFlags(&s1, cudaStreamNonBlocking);
        cudaEventCreateWithFlags(&evRoot, cudaEventDisableTiming);
        cudaEventCreateWithFlags(&evS1, cudaEventDisableTiming);
        init_done = true;
    }

    int nblk_img4 = (BN * NPIX / 4 + TPB - 1) / TPB;
    dim3 wgrid(16, 16, BN), wblk(32, 8);

    // fork: side branch fully independent of the main chain
    cudaEventRecord(evRoot, 0);
    cudaStreamWaitEvent(s1, evRoot, 0);

    // side branch s1: memset + srcbox + mask1 (boxes computed in-block)
    cudaMemsetAsync(seg3, 0, (size_t)NM * BN * NPIX * sizeof(float), s1);
    k_srcbox<<<dim3(8, NM), TPB, 0, s1>>>(masks);
    k_mask1<<<dim3(8, NM * BN), TPB, 0, s1>>>(masks, ro);
    cudaEventRecord(evS1, s1);

    // main chain: resize -> warpA -> warpB -> warpC -> (join) mask23 -> revise
    k_resize4<<<nblk_img4, TPB>>>(base, seg0);
    k_warp4sq<<<wgrid, wblk>>>(seg0, bufA, nullptr, tr);    // inv(translation)
    k_warp4sq<<<wgrid, wblk>>>(bufA, bufB, nullptr, ro);    // inv(rotation)
    k_warp4sq<<<wgrid, wblk>>>(bufB, seg1, seg2, sc);       // inv(shear)

    cudaStreamWaitEvent(0, evS1, 0);
    k_mask23<<<NM * BN, 1024>>>(seg1, seg3, sc, ro);
    k_revise<<<BN, 1024, PATCH * PATCH * sizeof(float)>>>(seg2, adj, sc);
}

// round 16
// speedup vs baseline: 3.2115x; 1.0107x over previous
#include <cuda_runtime.h>
#include <math.h>

#define BN 16
#define UPD 512
#define NPIX (UPD*UPD)
#define PATCH 120
#define NM 4
#define TPB 256

// ---------------- static device scratch (zero-initialized at load) ----------------
__device__ float g_inv[3*BN*6];                 // inverse thetas: [which][b][6] (0=sc,1=ro,2=tr)
__device__ float g_bufA[BN*NPIX];               // pred_trans
__device__ float g_bufB[BN*NPIX];               // pred_rot
__device__ float g_rm2[NM*BN*NPIX];             // mask after g2 sample (zero outside boxes)
__device__ int4  g_srcpart[NM*8];               // per-j partial src bboxes
__device__ float g_com[NM*BN*3];                // per (j,b): tot, sx, sy

// ---------------- helpers ----------------
__device__ __forceinline__ float bilin_sample(const float* __restrict__ s,
                                              float gx, float gy, int H, int W) {
    // torch grid_sample: bilinear, zero padding, align_corners=False
    float x = ((gx + 1.0f) * (float)W - 1.0f) * 0.5f;
    float y = ((gy + 1.0f) * (float)H - 1.0f) * 0.5f;
    float xf = floorf(x), yf = floorf(y);
    int x0 = (int)xf, y0 = (int)yf;
    float wx = x - xf, wy = y - yf;
    int x1 = x0 + 1, y1 = y0 + 1;
    bool xi0 = (x0 >= 0) && (x0 < W);
    bool xi1 = (x1 >= 0) && (x1 < W);
    bool yi0 = (y0 >= 0) && (y0 < H);
    bool yi1 = (y1 >= 0) && (y1 < H);
    float v00 = 0.f, v01 = 0.f, v10 = 0.f, v11 = 0.f;
    if (yi0) {
        const float* row = s + y0 * W;
        if (xi0) v00 = __ldg(row + x0);
        if (xi1) v01 = __ldg(row + x1);
    }
    if (yi1) {
        const float* row = s + y1 * W;
        if (xi0) v10 = __ldg(row + x0);
        if (xi1) v11 = __ldg(row + x1);
    }
    return (1.f - wx) * (1.f - wy) * v00 + wx * (1.f - wy) * v01
         + (1.f - wx) * wy * v10 + wx * wy * v11;
}

__device__ __forceinline__ void preimage_px(const float* th,
        float ya, float yb, float xa, float xb,
        int& ir0, int& ir1, int& ic0, int& ic1) {
    float gxa = (2.f * xa + 1.f) / 512.f - 1.f, gxb = (2.f * xb + 1.f) / 512.f - 1.f;
    float gya = (2.f * ya + 1.f) / 512.f - 1.f, gyb = (2.f * yb + 1.f) / 512.f - 1.f;
    float det = th[0] * th[4] - th[1] * th[3];
    float Xmin = 1e30f, Xmax = -1e30f, Ymin = 1e30f, Ymax = -1e30f;
    #pragma unroll
    for (int u = 0; u < 4; u++) {
        float gx = (u & 1) ? gxb : gxa;
        float gy = (u & 2) ? gyb : gya;
        float rx = gx - th[2], ry = gy - th[5];
        float X = ( th[4] * rx - th[1] * ry) / det;
        float Y = (-th[3] * rx + th[0] * ry) / det;
        Xmin = fminf(Xmin, X); Xmax = fmaxf(Xmax, X);
        Ymin = fminf(Ymin, Y); Ymax = fmaxf(Ymax, Y);
    }
    float jmin = ((Xmin + 1.f) * 512.f - 1.f) * 0.5f;
    float jmax = ((Xmax + 1.f) * 512.f - 1.f) * 0.5f;
    float imin = ((Ymin + 1.f) * 512.f - 1.f) * 0.5f;
    float imax = ((Ymax + 1.f) * 512.f - 1.f) * 0.5f;
    ir0 = max(0,   (int)floorf(imin) - 1);
    ir1 = min(511, (int)ceilf(imax) + 1);
    ic0 = max(0,   (int)floorf(jmin) - 1);
    ic1 = min(511, (int)ceilf(jmax) + 1);
}

__device__ __forceinline__ void combine_srcbox(int j, int& r0, int& r1, int& c0, int& c1) {
    r0 = 1 << 20; r1 = -1; c0 = 1 << 20; c1 = -1;
    #pragma unroll
    for (int k = 0; k < 8; k++) {
        int4 p = g_srcpart[j * 8 + k];
        r0 = min(r0, p.x); r1 = max(r1, p.y);
        c0 = min(c0, p.z); c1 = max(c1, p.w);
    }
}

// core box1 (pre-dilation) for (j,b): preimage of src bbox through inv(rotation)
__device__ __forceinline__ bool box1_core(int j, const float* ithro,
                                          int& a0, int& a1, int& b0, int& b1) {
    int r0, r1, c0, c1;
    combine_srcbox(j, r0, r1, c0, c1);
    if (r1 < r0) return false;
    preimage_px(ithro, (float)r0 - 1.f, (float)r1 + 1.f,
                (float)c0 - 1.f, (float)c1 + 1.f, a0, a1, b0, b1);
    return true;
}

// ---------------- K0: 2x3 affine inverses (side stream, hidden under resize) ----------------
__global__ void k_inv(const float* __restrict__ sc, const float* __restrict__ ro,
                      const float* __restrict__ tr) {
    int t = threadIdx.x;
    if (t >= 3 * BN) return;
    int w = t / BN, b = t % BN;
    const float* src = (w == 0) ? sc : ((w == 1) ? ro : tr);
    const float* m = src + b * 6;
    float a = m[0], bb = m[1], c = m[2], d = m[3], e = m[4], f = m[5];
    float det = a * e - bb * d;
    float ia = e / det, ib = -bb / det, id = -d / det, ie = a / det;
    float ic  = -(ia * c + ib * f);
    float iff = -(id * c + ie * f);
    float* o = g_inv + t * 6;
    o[0] = ia; o[1] = ib; o[2] = ic; o[3] = id; o[4] = ie; o[5] = iff;
}

// ---------------- source mask bbox (partials; side stream) ----------------
__global__ void k_srcbox(const float* __restrict__ masks) {
    int j = blockIdx.y, seg = blockIdx.x;
    const float* m = masks + j * NPIX;
    int base = seg * (NPIX / 8);
    int rmin = 1 << 20, rmax = -1, cmin = 1 << 20, cmax = -1;
    for (int k = threadIdx.x; k < NPIX / 8; k += TPB) {
        int g = base + k;
        if (m[g] != 0.0f) {
            int r = g >> 9, c = g & 511;
            rmin = min(rmin, r); rmax = max(rmax, r);
            cmin = min(cmin, c); cmax = max(cmax, c);
        }
    }
    __shared__ int s0[TPB], s1[TPB], s2[TPB], s3[TPB];
    s0[threadIdx.x] = rmin; s1[threadIdx.x] = rmax;
    s2[threadIdx.x] = cmin; s3[threadIdx.x] = cmax;
    __syncthreads();
    for (int s = TPB / 2; s > 0; s >>= 1) {
        if (threadIdx.x < s) {
            s0[threadIdx.x] = min(s0[threadIdx.x], s0[threadIdx.x + s]);
            s1[threadIdx.x] = max(s1[threadIdx.x], s1[threadIdx.x + s]);
            s2[threadIdx.x] = min(s2[threadIdx.x], s2[threadIdx.x + s]);
            s3[threadIdx.x] = max(s3[threadIdx.x], s3[threadIdx.x + s]);
        }
        __syncthreads();
    }
    if (threadIdx.x == 0)
        g_srcpart[j * 8 + seg] = make_int4(s0[0], s1[0], s2[0], s3[0]);
}

// ---------------- K1: jax.image.resize linear, 4 outputs/thread ----------------
__global__ void k_resize4(const float* __restrict__ base, float* __restrict__ out) {
    int idx = blockIdx.x * blockDim.x + threadIdx.x;
    if (idx >= BN * NPIX / 4) return;
    int b = idx / (NPIX / 4), r4 = idx - b * (NPIX / 4);
    int i = r4 >> 7;
    int j0 = (r4 & 127) * 4;
    float fy = (i + 0.5f) * 0.25f - 0.5f;
    fy = fminf(fmaxf(fy, 0.f), 127.f);
    int y0 = (int)fy;
    float wy = fy - (float)y0;
    int y1 = min(y0 + 1, 127);
    const float* p = base + b * 128 * 128;
    const float* r0 = p + y0 * 128;
    const float* r1 = p + y1 * 128;
    float4 o;
    #pragma unroll
    for (int q = 0; q < 4; q++) {
        float fx = (j0 + q + 0.5f) * 0.25f - 0.5f;
        fx = fminf(fmaxf(fx, 0.f), 127.f);
        int x0 = (int)fx;
        float wx = fx - (float)x0;
        int x1 = min(x0 + 1, 127);
        float top = (1.f - wx) * __ldg(r0 + x0) + wx * __ldg(r0 + x1);
        float bot = (1.f - wx) * __ldg(r1 + x0) + wx * __ldg(r1 + x1);
        ((float*)&o)[q] = (1.f - wy) * top + wy * bot;
    }
    ((float4*)out)[idx] = o;
}

// ---------------- image warp, square 32x32 tile, 4 rows/thread ----------------
// Theta read per-thread from precomputed g_inv (measured-best round-12 form).
__global__ void k_warp4sq(const float* __restrict__ src, float* __restrict__ dst,
                          float* __restrict__ dst2, int thoff) {
    int b = blockIdx.z;
    int i0 = blockIdx.y * 32 + threadIdx.y;
    int j  = blockIdx.x * 32 + threadIdx.x;
    const float* th = g_inv + (thoff + b) * 6;
    float t0 = th[0], t1 = th[1], t2 = th[2], t3 = th[3], t4 = th[4], t5 = th[5];
    float X = (float)(2 * j + 1) / 512.0f - 1.0f;
    float gxX = t0 * X + t2;
    float gyX = t3 * X + t5;
    const float* s = src + b * NPIX;
    float v[4];
    #pragma unroll
    for (int q = 0; q < 4; q++) {
        int i = i0 + q * 8;
        float Y = (float)(2 * i + 1) / 512.0f - 1.0f;
        v[q] = bilin_sample(s, gxX + t1 * Y, gyX + t4 * Y, UPD, UPD);
    }
    int base_idx = b * NPIX + (i0 << 9) + j;
    #pragma unroll
    for (int q = 0; q < 4; q++) {
        dst[base_idx + (q << 12)] = v[q];
        if (dst2) dst2[base_idx + (q << 12)] = v[q];
    }
}

// ---------------- mask stage 1 (box-restricted, side stream) ----------------
// Box computed in-block from g_srcpart + g_inv (no k_boxes node).
__global__ void k_mask1(const float* __restrict__ masks) {
    __shared__ int sbx[4];     // w0, w2, bh, bw
    int jb = blockIdx.y;
    int j = jb / BN, b = jb % BN;
    const float* th = g_inv + (BN + b) * 6;
    if (threadIdx.x == 0) {
        int a0, a1, b0, b1;
        if (box1_core(j, th, a0, a1, b0, b1)) {
            int w0 = max(0, a0 - 2), w1 = min(511, a1 + 2);
            int w2 = max(0, b0 - 2), w3 = min(511, b1 + 2);
            sbx[0] = w0; sbx[1] = w2;
            sbx[2] = w1 - w0 + 1; sbx[3] = w3 - w2 + 1;
        } else {
            sbx[0] = sbx[1] = sbx[2] = sbx[3] = 0;
        }
    }
    __syncthreads();
    int w0 = sbx[0], w2 = sbx[1], bh = sbx[2], bw = sbx[3];
    int area = bh * bw;
    float t0 = th[0], t1 = th[1], t2 = th[2], t3 = th[3], t4 = th[4], t5 = th[5];
    const float* s = masks + j * NPIX;
    float* dst = g_rm2 + (size_t)jb * NPIX;
    for (int t = blockIdx.x * TPB + threadIdx.x; t < area; t += 8 * TPB) {
        int i = w0 + t / bw, jj = w2 + t % bw;
        float X = (float)(2 * jj + 1) / 512.0f - 1.0f;
        float Y = (float)(2 * i + 1) / 512.0f - 1.0f;
        dst[(i << 9) + jj] = bilin_sample(s, t0 * X + t1 * Y + t2,
                                             t3 * X + t4 * Y + t5, UPD, UPD);
    }
}

// ---------------- FUSED mask stage 2 + threshold + COM: one block per (j,b) ----------------
__global__ void k_mask23(const float* __restrict__ img_all, float* __restrict__ mrot) {
    int jb = blockIdx.x;
    int j = jb / BN, b = jb % BN;
    int tid = threadIdx.x;
    const int NT = 1024;
    __shared__ float sh1[NT], sh2[NT], sh3[NT];
    __shared__ float sh_thr;
    __shared__ int sbx[4];     // d0, e0, bh, bw

    const float* th = g_inv + b * 6;      // inv(scaler_shear)
    if (tid == 0) {
        const float* thro = g_inv + (BN + b) * 6;
        int a0, a1, b0, b1;
        if (box1_core(j, thro, a0, a1, b0, b1)) {
            int dd0, dd1, ee0, ee1;
            preimage_px(th, (float)a0 - 1.f, (float)a1 + 1.f,
                        (float)b0 - 1.f, (float)b1 + 1.f, dd0, dd1, ee0, ee1);
            int d0 = max(0, dd0 - 1), d1 = min(511, dd1 + 1);
            int e0 = max(0, ee0 - 1), e1 = min(511, ee1 + 1);
            sbx[0] = d0; sbx[1] = e0;
            sbx[2] = d1 - d0 + 1; sbx[3] = e1 - e0 + 1;
        } else {
            sbx[0] = sbx[1] = sbx[2] = sbx[3] = 0;
        }
    }
    __syncthreads();
    int d0 = sbx[0], e0 = sbx[1], bh = sbx[2], bw = sbx[3];
    int area = bh * bw;
    float t0 = th[0], t1 = th[1], t2 = th[2], t3 = th[3], t4 = th[4], t5 = th[5];
    const float* src = g_rm2 + (size_t)jb * NPIX;
    const float* img = img_all + b * NPIX;
    float* dst = mrot + (size_t)jb * NPIX;
    float sn = 0.f, sm = 0.f;
    for (int t = tid; t < area; t += NT) {
        int i = d0 + t / bw, jj = e0 + t % bw;
        float X = (float)(2 * jj + 1) / 512.0f - 1.0f;
        float Y = (float)(2 * i + 1) / 512.0f - 1.0f;
        float v = bilin_sample(src, t0 * X + t1 * Y + t2, t3 * X + t4 * Y + t5, UPD, UPD);
        int g = (i << 9) + jj;
        bool on = (v >= 0.5f);
        dst[g] = on ? 1.0f : 0.0f;
        if (on) { sn += img[g]; sm += 1.0f; }
    }
    sh1[tid] = sn; sh2[tid] = sm;
    __syncthreads();
    for (int s = NT / 2; s > 0; s >>= 1) {
        if (tid < s) { sh1[tid] += sh1[tid + s]; sh2[tid] += sh2[tid + s]; }
        __syncthreads();
    }
    if (tid == 0) sh_thr = (sh1[0] / fmaxf(sh2[0], 1.0f)) * 1.5f;
    __syncthreads();
    float thr = sh_thr;

    float st = 0.f, sx = 0.f, sy = 0.f;
    for (int t = tid; t < area; t += NT) {
        int i = d0 + t / bw, jj = e0 + t % bw;
        int g = (i << 9) + jj;
        if (dst[g] > 0.5f) {
            float nv = img[g];
            if (nv > thr) {
                st += nv;
                sx += nv * (float)i;
                sy += nv * (float)jj;
            }
        }
    }
    sh1[tid] = st; sh2[tid] = sx; sh3[tid] = sy;
    __syncthreads();
    for (int s = NT / 2; s > 0; s >>= 1) {
        if (tid < s) {
            sh1[tid] += sh1[tid + s];
            sh2[tid] += sh2[tid + s];
            sh3[tid] += sh3[tid + s];
        }
        __syncthreads();
    }
    if (tid == 0) {
        g_com[jb * 3 + 0] = sh1[0];
        g_com[jb * 3 + 1] = sh2[0];
        g_com[jb * 3 + 2] = sh3[0];
    }
}

// ---------------- revise: one block per batch item; patch in dynamic smem ----------------
__global__ void k_revise(float* __restrict__ rev, const float* __restrict__ adj) {
    extern __shared__ float patch[];   // PATCH*PATCH floats = 57.6KB
    __shared__ int sh_xy[2];
    int b = blockIdx.x;
    int tid = threadIdx.x;
    float a = adj[b];
    float* img = rev + b * NPIX;
    const float* th = g_inv + b * 6;   // inv(scaler_shear)
    for (int j = 0; j < NM; j++) {
        if (tid == 0) {
            int o = (j * BN + b) * 3;
            float tot = g_com[o] + 1e-8f;
            float cx = g_com[o + 1] / tot, cy = g_com[o + 2] / tot;
            int x0 = __float2int_rn(cx) - 60;            // round half to even
            int y0 = __float2int_rn(cy) - 60;
            x0 = min(max(x0, 0), UPD - PATCH);           // dynamic_slice clamping
            y0 = min(max(y0, 0), UPD - PATCH);
            sh_xy[0] = x0; sh_xy[1] = y0;
        }
        __syncthreads();
        int x0 = sh_xy[0], y0 = sh_xy[1];
        for (int t = tid; t < PATCH * PATCH; t += blockDim.x) {
            int p = t / PATCH, q = t - p * PATCH;
            float v = img[(x0 + p) * UPD + (y0 + q)];
            int dp = p - 60, dq = q - 60;
            if (dp * dp + dq * dq <= 16) v = v / a;
            patch[t] = v;
        }
        __syncthreads();
        for (int t = tid; t < PATCH * PATCH; t += blockDim.x) {
            int p = t / PATCH, q = t - p * PATCH;
            float X = (float)(2 * q + 1) / 120.0f - 1.0f;
            float Y = (float)(2 * p + 1) / 120.0f - 1.0f;
            float gx = th[0] * X + th[1] * Y + th[2];
            float gy = th[3] * X + th[4] * Y + th[5];
            float x = ((gx + 1.0f) * 120.0f - 1.0f) * 0.5f;
            float y = ((gy + 1.0f) * 120.0f - 1.0f) * 0.5f;
            float xf = floorf(x), yf = floorf(y);
            int xx0 = (int)xf, yy0 = (int)yf;
            float wx = x - xf, wy = y - yf;
            int xx1 = xx0 + 1, yy1 = yy0 + 1;
            bool xi0 = (xx0 >= 0) && (xx0 < PATCH);
            bool xi1 = (xx1 >= 0) && (xx1 < PATCH);
            bool yi0 = (yy0 >= 0) && (yy0 < PATCH);
            bool yi1 = (yy1 >= 0) && (yy1 < PATCH);
            float v00 = (yi0 && xi0) ? patch[yy0 * PATCH + xx0] : 0.f;
            float v01 = (yi0 && xi1) ? patch[yy0 * PATCH + xx1] : 0.f;
            float v10 = (yi1 && xi0) ? patch[yy1 * PATCH + xx0] : 0.f;
            float v11 = (yi1 && xi1) ? patch[yy1 * PATCH + xx1] : 0.f;
            float v = (1.f - wx) * (1.f - wy) * v00 + wx * (1.f - wy) * v01
                    + (1.f - wx) * wy * v10 + wx * wy * v11;
            img[(x0 + p) * UPD + (y0 + q)] = v;
        }
        __syncthreads();
    }
}

// ---------------- launch ----------------
extern "C" void kernel_launch(void* const* d_in, const int* in_sizes, int n_in,
                              void* d_out, int out_size) {
    const float* base  = (const float*)d_in[0];
    const float* sc    = (const float*)d_in[1];
    const float* ro    = (const float*)d_in[2];
    const float* tr    = (const float*)d_in[3];
    const float* adj   = (const float*)d_in[4];
    const float* masks = (const float*)d_in[5];
    float* out = (float*)d_out;
    float* seg0 = out;                           // base_inp
    float* seg1 = out + (size_t)BN * NPIX;       // pred_input
    float* seg2 = out + (size_t)2 * BN * NPIX;   // pred_revise
    float* seg3 = out + (size_t)3 * BN * NPIX;   // masks_rot

    float *bufA, *bufB;
    cudaGetSymbolAddress((void**)&bufA, g_bufA);
    cudaGetSymbolAddress((void**)&bufB, g_bufB);

    // One-time resources (created on the uncaptured correctness call; reused
    // during capture — proven-clean 1-stream/3-event configuration, round 6).
    static cudaStream_t s1 = nullptr;
    static cudaEvent_t evRoot, evInv, evS1;
    static bool init_done = false;
    if (!init_done) {
        cudaFuncSetAttribute(k_revise, cudaFuncAttributeMaxDynamicSharedMemorySize,
                             PATCH * PATCH * (int)sizeof(float));
        cudaStreamCreateWithFlags(&s1, cudaStreamNonBlocking);
        cudaEventCreateWithFlags(&evRoot, cudaEventDisableTiming);
        cudaEventCreateWithFlags(&evInv, cudaEventDisableTiming);
        cudaEventCreateWithFlags(&evS1, cudaEventDisableTiming);
        init_done = true;
    }

    int nblk_img4 = (BN * NPIX / 4 + TPB - 1) / TPB;
    dim3 wgrid(16, 16, BN), wblk(32, 8);

    // fork
    cudaEventRecord(evRoot, 0);
    cudaStreamWaitEvent(s1, evRoot, 0);

    // side branch s1: k_inv FIRST (hidden under resize), then memset/srcbox/mask1
    k_inv<<<1, 64, 0, s1>>>(sc, ro, tr);
    cudaEventRecord(evInv, s1);
    cudaMemsetAsync(seg3, 0, (size_t)NM * BN * NPIX * sizeof(float), s1);
    k_srcbox<<<dim3(8, NM), TPB, 0, s1>>>(masks);
    k_mask1<<<dim3(8, NM * BN), TPB, 0, s1>>>(masks);
    cudaEventRecord(evS1, s1);

    // main chain: resize runs concurrently with k_inv; warpA waits on evInv
    // (an edge, not a critical-path node — resize >> k_inv so it's free).
    k_resize4<<<nblk_img4, TPB>>>(base, seg0);
    cudaStreamWaitEvent(0, evInv, 0);
    k_warp4sq<<<wgrid, wblk>>>(seg0, bufA, nullptr, 2 * BN);    // inv(translation)
    k_warp4sq<<<wgrid, wblk>>>(bufA, bufB, nullptr, 1 * BN);    // inv(rotation)
    k_warp4sq<<<wgrid, wblk>>>(bufB, seg1, seg2, 0);            // inv(shear)

    cudaStreamWaitEvent(0, evS1, 0);
    k_mask23<<<NM * BN, 1024>>>(seg1, seg3);
    k_revise<<<BN, 1024, PATCH * PATCH * sizeof(float)>>>(seg2, adj);
}

// round 17
// speedup vs baseline: 3.2330x; 1.0067x over previous
#include <cuda_runtime.h>
#include <cooperative_groups.h>
#include <math.h>

namespace cg = cooperative_groups;

#define BN 16
#define UPD 512
#define NPIX (UPD*UPD)
#define PATCH 120
#define NM 4
#define TPB 256

// ---------------- static device scratch (zero-initialized at load) ----------------
__device__ float g_inv[3*BN*6];                 // inverse thetas: [which][b][6] (0=sc,1=ro,2=tr)
__device__ float g_bufA[BN*NPIX];               // pred_trans
__device__ float g_bufB[BN*NPIX];               // pred_rot
__device__ float g_rm2[NM*BN*NPIX];             // mask after g2 sample (zero outside boxes)
__device__ int4  g_srcpart[NM*8];               // per-j partial src bboxes
__device__ float g_com[NM*BN*3];                // per (j,b): tot, sx, sy

// ---------------- helpers ----------------
// bilinear from precomputed pixel coords (zero padding) — checked path
__device__ __forceinline__ float bilin_xy(const float* __restrict__ s,
                                          float x, float y, int H, int W) {
    float xf = floorf(x), yf = floorf(y);
    int x0 = (int)xf, y0 = (int)yf;
    float wx = x - xf, wy = y - yf;
    int x1 = x0 + 1, y1 = y0 + 1;
    bool xi0 = (x0 >= 0) && (x0 < W);
    bool xi1 = (x1 >= 0) && (x1 < W);
    bool yi0 = (y0 >= 0) && (y0 < H);
    bool yi1 = (y1 >= 0) && (y1 < H);
    float v00 = 0.f, v01 = 0.f, v10 = 0.f, v11 = 0.f;
    if (yi0) {
        const float* row = s + y0 * W;
        if (xi0) v00 = __ldg(row + x0);
        if (xi1) v01 = __ldg(row + x1);
    }
    if (yi1) {
        const float* row = s + y1 * W;
        if (xi0) v10 = __ldg(row + x0);
        if (xi1) v11 = __ldg(row + x1);
    }
    return (1.f - wx) * (1.f - wy) * v00 + wx * (1.f - wy) * v01
         + (1.f - wx) * wy * v10 + wx * wy * v11;
}

__device__ __forceinline__ float bilin_sample(const float* __restrict__ s,
                                              float gx, float gy, int H, int W) {
    float x = ((gx + 1.0f) * (float)W - 1.0f) * 0.5f;
    float y = ((gy + 1.0f) * (float)H - 1.0f) * 0.5f;
    return bilin_xy(s, x, y, H, W);
}

__device__ __forceinline__ void preimage_px(const float* th,
        float ya, float yb, float xa, float xb,
        int& ir0, int& ir1, int& ic0, int& ic1) {
    float gxa = (2.f * xa + 1.f) / 512.f - 1.f, gxb = (2.f * xb + 1.f) / 512.f - 1.f;
    float gya = (2.f * ya + 1.f) / 512.f - 1.f, gyb = (2.f * yb + 1.f) / 512.f - 1.f;
    float det = th[0] * th[4] - th[1] * th[3];
    float Xmin = 1e30f, Xmax = -1e30f, Ymin = 1e30f, Ymax = -1e30f;
    #pragma unroll
    for (int u = 0; u < 4; u++) {
        float gx = (u & 1) ? gxb : gxa;
        float gy = (u & 2) ? gyb : gya;
        float rx = gx - th[2], ry = gy - th[5];
        float X = ( th[4] * rx - th[1] * ry) / det;
        float Y = (-th[3] * rx + th[0] * ry) / det;
        Xmin = fminf(Xmin, X); Xmax = fmaxf(Xmax, X);
        Ymin = fminf(Ymin, Y); Ymax = fmaxf(Ymax, Y);
    }
    float jmin = ((Xmin + 1.f) * 512.f - 1.f) * 0.5f;
    float jmax = ((Xmax + 1.f) * 512.f - 1.f) * 0.5f;
    float imin = ((Ymin + 1.f) * 512.f - 1.f) * 0.5f;
    float imax = ((Ymax + 1.f) * 512.f - 1.f) * 0.5f;
    ir0 = max(0,   (int)floorf(imin) - 1);
    ir1 = min(511, (int)ceilf(imax) + 1);
    ic0 = max(0,   (int)floorf(jmin) - 1);
    ic1 = min(511, (int)ceilf(jmax) + 1);
}

__device__ __forceinline__ void combine_srcbox(int j, int& r0, int& r1, int& c0, int& c1) {
    r0 = 1 << 20; r1 = -1; c0 = 1 << 20; c1 = -1;
    #pragma unroll
    for (int k = 0; k < 8; k++) {
        int4 p = g_srcpart[j * 8 + k];
        r0 = min(r0, p.x); r1 = max(r1, p.y);
        c0 = min(c0, p.z); c1 = max(c1, p.w);
    }
}

__device__ __forceinline__ bool box1_core(int j, const float* ithro,
                                          int& a0, int& a1, int& b0, int& b1) {
    int r0, r1, c0, c1;
    combine_srcbox(j, r0, r1, c0, c1);
    if (r1 < r0) return false;
    preimage_px(ithro, (float)r0 - 1.f, (float)r1 + 1.f,
                (float)c0 - 1.f, (float)c1 + 1.f, a0, a1, b0, b1);
    return true;
}

// ---------------- K0: 2x3 affine inverses (side stream, hidden under resize) ----------------
__global__ void k_inv(const float* __restrict__ sc, const float* __restrict__ ro,
                      const float* __restrict__ tr) {
    int t = threadIdx.x;
    if (t >= 3 * BN) return;
    int w = t / BN, b = t % BN;
    const float* src = (w == 0) ? sc : ((w == 1) ? ro : tr);
    const float* m = src + b * 6;
    float a = m[0], bb = m[1], c = m[2], d = m[3], e = m[4], f = m[5];
    float det = a * e - bb * d;
    float ia = e / det, ib = -bb / det, id = -d / det, ie = a / det;
    float ic  = -(ia * c + ib * f);
    float iff = -(id * c + ie * f);
    float* o = g_inv + t * 6;
    o[0] = ia; o[1] = ib; o[2] = ic; o[3] = id; o[4] = ie; o[5] = iff;
}

// ---------------- source mask bbox (partials; side stream) ----------------
__global__ void k_srcbox(const float* __restrict__ masks) {
    int j = blockIdx.y, seg = blockIdx.x;
    const float* m = masks + j * NPIX;
    int base = seg * (NPIX / 8);
    int rmin = 1 << 20, rmax = -1, cmin = 1 << 20, cmax = -1;
    for (int k = threadIdx.x; k < NPIX / 8; k += TPB) {
        int g = base + k;
        if (m[g] != 0.0f) {
            int r = g >> 9, c = g & 511;
            rmin = min(rmin, r); rmax = max(rmax, r);
            cmin = min(cmin, c); cmax = max(cmax, c);
        }
    }
    __shared__ int s0[TPB], s1[TPB], s2[TPB], s3[TPB];
    s0[threadIdx.x] = rmin; s1[threadIdx.x] = rmax;
    s2[threadIdx.x] = cmin; s3[threadIdx.x] = cmax;
    __syncthreads();
    for (int s = TPB / 2; s > 0; s >>= 1) {
        if (threadIdx.x < s) {
            s0[threadIdx.x] = min(s0[threadIdx.x], s0[threadIdx.x + s]);
            s1[threadIdx.x] = max(s1[threadIdx.x], s1[threadIdx.x + s]);
            s2[threadIdx.x] = min(s2[threadIdx.x], s2[threadIdx.x + s]);
            s3[threadIdx.x] = max(s3[threadIdx.x], s3[threadIdx.x + s]);
        }
        __syncthreads();
    }
    if (threadIdx.x == 0)
        g_srcpart[j * 8 + seg] = make_int4(s0[0], s1[0], s2[0], s3[0]);
}

// ---------------- K1: jax.image.resize linear, 4 outputs/thread ----------------
__global__ void k_resize4(const float* __restrict__ base, float* __restrict__ out) {
    int idx = blockIdx.x * blockDim.x + threadIdx.x;
    if (idx >= BN * NPIX / 4) return;
    int b = idx / (NPIX / 4), r4 = idx - b * (NPIX / 4);
    int i = r4 >> 7;
    int j0 = (r4 & 127) * 4;
    float fy = (i + 0.5f) * 0.25f - 0.5f;
    fy = fminf(fmaxf(fy, 0.f), 127.f);
    int y0 = (int)fy;
    float wy = fy - (float)y0;
    int y1 = min(y0 + 1, 127);
    const float* p = base + b * 128 * 128;
    const float* r0 = p + y0 * 128;
    const float* r1 = p + y1 * 128;
    float4 o;
    #pragma unroll
    for (int q = 0; q < 4; q++) {
        float fx = (j0 + q + 0.5f) * 0.25f - 0.5f;
        fx = fminf(fmaxf(fx, 0.f), 127.f);
        int x0 = (int)fx;
        float wx = fx - (float)x0;
        int x1 = min(x0 + 1, 127);
        float top = (1.f - wx) * __ldg(r0 + x0) + wx * __ldg(r0 + x1);
        float bot = (1.f - wx) * __ldg(r1 + x0) + wx * __ldg(r1 + x1);
        ((float*)&o)[q] = (1.f - wy) * top + wy * bot;
    }
    ((float4*)out)[idx] = o;
}

// ---------------- image warp, 32x32 tile, 4 rows/thread, interior fast path ----------------
__global__ void k_warp4sq(const float* __restrict__ src, float* __restrict__ dst,
                          float* __restrict__ dst2, int thoff) {
    int b = blockIdx.z;
    int i0 = blockIdx.y * 32 + threadIdx.y;
    int j  = blockIdx.x * 32 + threadIdx.x;
    const float* th = g_inv + (thoff + b) * 6;
    float t0 = th[0], t1 = th[1], t2 = th[2], t3 = th[3], t4 = th[4], t5 = th[5];
    float X = (float)(2 * j + 1) / 512.0f - 1.0f;
    float gxX = t0 * X + t2;
    float gyX = t3 * X + t5;
    const float* s = src + b * NPIX;
    float xs[4], ys[4];
    #pragma unroll
    for (int q = 0; q < 4; q++) {
        int i = i0 + q * 8;
        float Y = (float)(2 * i + 1) / 512.0f - 1.0f;
        float gx = gxX + t1 * Y;
        float gy = gyX + t4 * Y;
        xs[q] = ((gx + 1.0f) * 512.0f - 1.0f) * 0.5f;
        ys[q] = ((gy + 1.0f) * 512.0f - 1.0f) * 0.5f;
    }
    float xmn = fminf(fminf(xs[0], xs[1]), fminf(xs[2], xs[3]));
    float xmx = fmaxf(fmaxf(xs[0], xs[1]), fmaxf(xs[2], xs[3]));
    float ymn = fminf(fminf(ys[0], ys[1]), fminf(ys[2], ys[3]));
    float ymx = fmaxf(fmaxf(ys[0], ys[1]), fmaxf(ys[2], ys[3]));
    float v[4];
    if (xmn >= 0.f && xmx < 511.f && ymn >= 0.f && ymx < 511.f) {
        // all 16 taps provably in-bounds: no predicates
        #pragma unroll
        for (int q = 0; q < 4; q++) {
            float xf = floorf(xs[q]), yf = floorf(ys[q]);
            int x0 = (int)xf, y0 = (int)yf;
            float wx = xs[q] - xf, wy = ys[q] - yf;
            const float* r0 = s + (y0 << 9) + x0;
            float v00 = __ldg(r0), v01 = __ldg(r0 + 1);
            float v10 = __ldg(r0 + 512), v11 = __ldg(r0 + 513);
            v[q] = (1.f - wx) * (1.f - wy) * v00 + wx * (1.f - wy) * v01
                 + (1.f - wx) * wy * v10 + wx * wy * v11;
        }
    } else {
        #pragma unroll
        for (int q = 0; q < 4; q++)
            v[q] = bilin_xy(s, xs[q], ys[q], UPD, UPD);
    }
    int base_idx = b * NPIX + (i0 << 9) + j;
    #pragma unroll
    for (int q = 0; q < 4; q++) {
        dst[base_idx + (q << 12)] = v[q];
        if (dst2) dst2[base_idx + (q << 12)] = v[q];
    }
}

// ---------------- mask stage 1 (box-restricted, side stream) ----------------
__global__ void k_mask1(const float* __restrict__ masks) {
    __shared__ int sbx[4];
    int jb = blockIdx.y;
    int j = jb / BN, b = jb % BN;
    const float* th = g_inv + (BN + b) * 6;
    if (threadIdx.x == 0) {
        int a0, a1, b0, b1;
        if (box1_core(j, th, a0, a1, b0, b1)) {
            int w0 = max(0, a0 - 2), w1 = min(511, a1 + 2);
            int w2 = max(0, b0 - 2), w3 = min(511, b1 + 2);
            sbx[0] = w0; sbx[1] = w2;
            sbx[2] = w1 - w0 + 1; sbx[3] = w3 - w2 + 1;
        } else {
            sbx[0] = sbx[1] = sbx[2] = sbx[3] = 0;
        }
    }
    __syncthreads();
    int w0 = sbx[0], w2 = sbx[1], bh = sbx[2], bw = sbx[3];
    int area = bh * bw;
    float t0 = th[0], t1 = th[1], t2 = th[2], t3 = th[3], t4 = th[4], t5 = th[5];
    const float* s = masks + j * NPIX;
    float* dst = g_rm2 + (size_t)jb * NPIX;
    for (int t = blockIdx.x * TPB + threadIdx.x; t < area; t += 8 * TPB) {
        int i = w0 + t / bw, jj = w2 + t % bw;
        float X = (float)(2 * jj + 1) / 512.0f - 1.0f;
        float Y = (float)(2 * i + 1) / 512.0f - 1.0f;
        dst[(i << 9) + jj] = bilin_sample(s, t0 * X + t1 * Y + t2,
                                             t3 * X + t4 * Y + t5, UPD, UPD);
    }
}

// ---------------- TAIL (cooperative): mask23 for all (j,b), grid.sync, revise ----------------
__global__ void k_tail(const float* __restrict__ img_all, float* __restrict__ mrot,
                       float* rev, const float* __restrict__ adj) {
    cg::grid_group grid = cg::this_grid();
    extern __shared__ float patch[];   // 57.6KB, used in the revise phase
    const int NT = 1024;
    __shared__ float sh1[NT], sh2[NT], sh3[NT];
    __shared__ float sh_thr;
    __shared__ int sbx[4];
    __shared__ int sh_xy[2];
    int tid = threadIdx.x;

    // ===== phase A: mask stage2 + threshold + COM (bid = jb in 0..63) =====
    {
        int jb = blockIdx.x;
        int j = jb / BN, b = jb % BN;
        const float* th = g_inv + b * 6;      // inv(scaler_shear)
        if (tid == 0) {
            const float* thro = g_inv + (BN + b) * 6;
            int a0, a1, b0, b1;
            if (box1_core(j, thro, a0, a1, b0, b1)) {
                int dd0, dd1, ee0, ee1;
                preimage_px(th, (float)a0 - 1.f, (float)a1 + 1.f,
                            (float)b0 - 1.f, (float)b1 + 1.f, dd0, dd1, ee0, ee1);
                int d0 = max(0, dd0 - 1), d1 = min(511, dd1 + 1);
                int e0 = max(0, ee0 - 1), e1 = min(511, ee1 + 1);
                sbx[0] = d0; sbx[1] = e0;
                sbx[2] = d1 - d0 + 1; sbx[3] = e1 - e0 + 1;
            } else {
                sbx[0] = sbx[1] = sbx[2] = sbx[3] = 0;
            }
        }
        __syncthreads();
        int d0 = sbx[0], e0 = sbx[1], bh = sbx[2], bw = sbx[3];
        int area = bh * bw;
        float t0 = th[0], t1 = th[1], t2 = th[2], t3 = th[3], t4 = th[4], t5 = th[5];
        const float* src = g_rm2 + (size_t)jb * NPIX;
        const float* img = img_all + b * NPIX;
        float* dst = mrot + (size_t)jb * NPIX;
        float sn = 0.f, sm = 0.f;
        for (int t = tid; t < area; t += NT) {
            int i = d0 + t / bw, jj = e0 + t % bw;
            float X = (float)(2 * jj + 1) / 512.0f - 1.0f;
            float Y = (float)(2 * i + 1) / 512.0f - 1.0f;
            float v = bilin_sample(src, t0 * X + t1 * Y + t2, t3 * X + t4 * Y + t5, UPD, UPD);
            int g = (i << 9) + jj;
            bool on = (v >= 0.5f);
            dst[g] = on ? 1.0f : 0.0f;
            if (on) { sn += img[g]; sm += 1.0f; }
        }
        sh1[tid] = sn; sh2[tid] = sm;
        __syncthreads();
        for (int s = NT / 2; s > 0; s >>= 1) {
            if (tid < s) { sh1[tid] += sh1[tid + s]; sh2[tid] += sh2[tid + s]; }
            __syncthreads();
        }
        if (tid == 0) sh_thr = (sh1[0] / fmaxf(sh2[0], 1.0f)) * 1.5f;
        __syncthreads();
        float thr = sh_thr;

        float st = 0.f, sx = 0.f, sy = 0.f;
        for (int t = tid; t < area; t += NT) {
            int i = d0 + t / bw, jj = e0 + t % bw;
            int g = (i << 9) + jj;
            if (dst[g] > 0.5f) {
                float nv = img[g];
                if (nv > thr) {
                    st += nv;
                    sx += nv * (float)i;
                    sy += nv * (float)jj;
                }
            }
        }
        sh1[tid] = st; sh2[tid] = sx; sh3[tid] = sy;
        __syncthreads();
        for (int s = NT / 2; s > 0; s >>= 1) {
            if (tid < s) {
                sh1[tid] += sh1[tid + s];
                sh2[tid] += sh2[tid + s];
                sh3[tid] += sh3[tid + s];
            }
            __syncthreads();
        }
        if (tid == 0) {
            g_com[jb * 3 + 0] = sh1[0];
            g_com[jb * 3 + 1] = sh2[0];
            g_com[jb * 3 + 2] = sh3[0];
        }
    }
    grid.sync();

    // ===== phase B: revise (bid < 16, one block per batch item) =====
    if (blockIdx.x < BN) {
        int b = blockIdx.x;
        float a = __ldg(adj + b);
        float* img = rev + b * NPIX;
        const float* th = g_inv + b * 6;
        for (int j = 0; j < NM; j++) {
            if (tid == 0) {
                int o = (j * BN + b) * 3;
                float tot = g_com[o] + 1e-8f;
                float cx = g_com[o + 1] / tot, cy = g_com[o + 2] / tot;
                int x0 = __float2int_rn(cx) - 60;            // round half to even
                int y0 = __float2int_rn(cy) - 60;
                x0 = min(max(x0, 0), UPD - PATCH);           // dynamic_slice clamping
                y0 = min(max(y0, 0), UPD - PATCH);
                sh_xy[0] = x0; sh_xy[1] = y0;
            }
            __syncthreads();
            int x0 = sh_xy[0], y0 = sh_xy[1];
            for (int t = tid; t < PATCH * PATCH; t += NT) {
                int p = t / PATCH, q = t - p * PATCH;
                float v = img[(x0 + p) * UPD + (y0 + q)];
                int dp = p - 60, dq = q - 60;
                if (dp * dp + dq * dq <= 16) v = v / a;
                patch[t] = v;
            }
            __syncthreads();
            for (int t = tid; t < PATCH * PATCH; t += NT) {
                int p = t / PATCH, q = t - p * PATCH;
                float X = (float)(2 * q + 1) / 120.0f - 1.0f;
                float Y = (float)(2 * p + 1) / 120.0f - 1.0f;
                float gx = th[0] * X + th[1] * Y + th[2];
                float gy = th[3] * X + th[4] * Y + th[5];
                float x = ((gx + 1.0f) * 120.0f - 1.0f) * 0.5f;
                float y = ((gy + 1.0f) * 120.0f - 1.0f) * 0.5f;
                float xf = floorf(x), yf = floorf(y);
                int xx0 = (int)xf, yy0 = (int)yf;
                float wx = x - xf, wy = y - yf;
                int xx1 = xx0 + 1, yy1 = yy0 + 1;
                bool xi0 = (xx0 >= 0) && (xx0 < PATCH);
                bool xi1 = (xx1 >= 0) && (xx1 < PATCH);
                bool yi0 = (yy0 >= 0) && (yy0 < PATCH);
                bool yi1 = (yy1 >= 0) && (yy1 < PATCH);
                float v00 = (yi0 && xi0) ? patch[yy0 * PATCH + xx0] : 0.f;
                float v01 = (yi0 && xi1) ? patch[yy0 * PATCH + xx1] : 0.f;
                float v10 = (yi1 && xi0) ? patch[yy1 * PATCH + xx0] : 0.f;
                float v11 = (yi1 && xi1) ? patch[yy1 * PATCH + xx1] : 0.f;
                float v = (1.f - wx) * (1.f - wy) * v00 + wx * (1.f - wy) * v01
                        + (1.f - wx) * wy * v10 + wx * wy * v11;
                img[(x0 + p) * UPD + (y0 + q)] = v;
            }
            __syncthreads();
        }
    }
}

// ---------------- launch ----------------
extern "C" void kernel_launch(void* const* d_in, const int* in_sizes, int n_in,
                              void* d_out, int out_size) {
    const float* base  = (const float*)d_in[0];
    const float* sc    = (const float*)d_in[1];
    const float* ro    = (const float*)d_in[2];
    const float* tr    = (const float*)d_in[3];
    const float* adj   = (const float*)d_in[4];
    const float* masks = (const float*)d_in[5];
    float* out = (float*)d_out;
    float* seg0 = out;                           // base_inp
    float* seg1 = out + (size_t)BN * NPIX;       // pred_input
    float* seg2 = out + (size_t)2 * BN * NPIX;   // pred_revise
    float* seg3 = out + (size_t)3 * BN * NPIX;   // masks_rot

    float *bufA, *bufB;
    cudaGetSymbolAddress((void**)&bufA, g_bufA);
    cudaGetSymbolAddress((void**)&bufB, g_bufB);

    // One-time resources (created on the uncaptured correctness call; reused
    // during capture — proven-clean 1-stream/3-event configuration).
    static cudaStream_t s1 = nullptr;
    static cudaEvent_t evRoot, evInv, evS1;
    static bool init_done = false;
    if (!init_done) {
        cudaFuncSetAttribute(k_tail, cudaFuncAttributeMaxDynamicSharedMemorySize,
                             PATCH * PATCH * (int)sizeof(float));
        cudaStreamCreateWithFlags(&s1, cudaStreamNonBlocking);
        cudaEventCreateWithFlags(&evRoot, cudaEventDisableTiming);
        cudaEventCreateWithFlags(&evInv, cudaEventDisableTiming);
        cudaEventCreateWithFlags(&evS1, cudaEventDisableTiming);
        init_done = true;
    }

    int nblk_img4 = (BN * NPIX / 4 + TPB - 1) / TPB;
    dim3 wgrid(16, 16, BN), wblk(32, 8);

    // fork
    cudaEventRecord(evRoot, 0);
    cudaStreamWaitEvent(s1, evRoot, 0);

    // side branch s1: k_inv FIRST (hidden under resize), then memset/srcbox/mask1
    k_inv<<<1, 64, 0, s1>>>(sc, ro, tr);
    cudaEventRecord(evInv, s1);
    cudaMemsetAsync(seg3, 0, (size_t)NM * BN * NPIX * sizeof(float), s1);
    k_srcbox<<<dim3(8, NM), TPB, 0, s1>>>(masks);
    k_mask1<<<dim3(8, NM * BN), TPB, 0, s1>>>(masks);
    cudaEventRecord(evS1, s1);

    // main chain
    k_resize4<<<nblk_img4, TPB>>>(base, seg0);
    cudaStreamWaitEvent(0, evInv, 0);
    k_warp4sq<<<wgrid, wblk>>>(seg0, bufA, nullptr, 2 * BN);    // inv(translation)
    k_warp4sq<<<wgrid, wblk>>>(bufA, bufB, nullptr, 1 * BN);    // inv(rotation)
    k_warp4sq<<<wgrid, wblk>>>(bufB, seg1, seg2, 0);            // inv(shear)

    cudaStreamWaitEvent(0, evS1, 0);
    // cooperative tail: mask23 (64 blocks) + grid.sync + revise (16 blocks)
    {
        void* args[4] = { (void*)&seg1, (void*)&seg3, (void*)&seg2, (void*)&adj };
        cudaLaunchCooperativeKernel((const void*)k_tail, dim3(NM * BN), dim3(1024),
                                    args, PATCH * PATCH * sizeof(float), (cudaStream_t)0);
    }
}